// round 8
// baseline (speedup 1.0000x reference)
#include <cuda_runtime.h>
#include <cuda_bf16.h>
#include <cstdint>
#include <math.h>

// Problem constants
#define D_NODE 256
#define D_PAIR 128
#define NHEAD  8
#define NSEQ   128
#define NRES   256
#define NROWS  (NSEQ * NRES)          // 32768
#define EPROJ  1024                    // 768 qkv + 256 gate

#define LOG2E 1.4426950408889634f

// Scratch
__device__ __nv_bfloat16 g_Mh[(size_t)NROWS * D_NODE];   // LN(M) hi
__device__ __nv_bfloat16 g_Ml[(size_t)NROWS * D_NODE];   // LN(M) lo
__device__ __nv_bfloat16 g_Wh[(size_t)EPROJ * D_NODE];   // [Wqkv;Wgate] hi
__device__ __nv_bfloat16 g_Wl[(size_t)EPROJ * D_NODE];   // lo
__device__ __nv_bfloat16 g_Oh[(size_t)D_NODE * D_NODE];  // W_o hi
__device__ __nv_bfloat16 g_Ol[(size_t)D_NODE * D_NODE];  // W_o lo
__device__ __nv_bfloat16 g_Xh[(size_t)NROWS * 768];      // q(scaled)|k|v hi
__device__ __nv_bfloat16 g_Xl[(size_t)NROWS * 768];      // lo
__device__ float         g_gate[(size_t)NROWS * 256];    // gate logits fp32
__device__ __nv_bfloat16 g_pbB[(size_t)NHEAD * NRES * NRES]; // pair bias*log2e [h][q][k]
__device__ __nv_bfloat16 g_Ah[(size_t)NROWS * D_NODE];   // gated attn out hi
__device__ __nv_bfloat16 g_Al[(size_t)NROWS * D_NODE];   // gated attn out lo

__device__ __forceinline__ uint32_t smem_u32(const void* p) {
    uint32_t a;
    asm("{ .reg .u64 t; cvta.to.shared.u64 t, %1; cvt.u32.u64 %0, t; }"
        : "=r"(a) : "l"(p));
    return a;
}

#define LDM_X4(r0, r1, r2, r3, addr)                                           \
    asm volatile("ldmatrix.sync.aligned.m8n8.x4.shared.b16 {%0,%1,%2,%3}, [%4];" \
                 : "=r"(r0), "=r"(r1), "=r"(r2), "=r"(r3) : "r"(addr))
#define LDM_A(v, addr) LDM_X4((v)[0], (v)[1], (v)[2], (v)[3], addr)

#define LDM_T(v, addr)                                                         \
    asm volatile("ldmatrix.sync.aligned.m8n8.x4.trans.shared.b16 {%0,%1,%2,%3}, [%4];" \
                 : "=r"((v)[0]), "=r"((v)[1]), "=r"((v)[2]), "=r"((v)[3]) : "r"(addr))

#define MMA_BF16(d, a, b0, b1)                                                 \
    asm volatile("mma.sync.aligned.m16n8k16.row.col.f32.bf16.bf16.f32 "        \
                 "{%0,%1,%2,%3}, {%4,%5,%6,%7}, {%8,%9}, {%0,%1,%2,%3};"       \
                 : "+f"((d)[0]), "+f"((d)[1]), "+f"((d)[2]), "+f"((d)[3])      \
                 : "r"((a)[0]), "r"((a)[1]), "r"((a)[2]), "r"((a)[3]),         \
                   "r"(b0), "r"(b1))

#define CP16(s, g)                                                             \
    asm volatile("cp.async.cg.shared.global [%0], [%1], 16;" :: "r"(s), "l"(g))
#define CP_COMMIT() asm volatile("cp.async.commit_group;" ::: "memory")

__device__ __forceinline__ uint32_t pk2(float lo, float hi) {
    uint32_t d;
    asm("cvt.rn.bf16x2.f32 %0, %1, %2;" : "=r"(d) : "f"(hi), "f"(lo));
    return d;
}
__device__ __forceinline__ float2 bfu2f2(uint32_t u) {
    __nv_bfloat162 b = *reinterpret_cast<__nv_bfloat162*>(&u);
    return make_float2(__bfloat162float(b.x), __bfloat162float(b.y));
}
__device__ __forceinline__ float ex2(float x) {
    float r;
    asm("ex2.approx.f32 %0, %1;" : "=f"(r) : "f"(x));
    return r;
}

__device__ __forceinline__ float warp_sum(float v) {
#pragma unroll
    for (int o = 16; o > 0; o >>= 1) v += __shfl_xor_sync(0xffffffffu, v, o);
    return v;
}

// ---------------------------------------------------------------------------
// Kernel 1 (fused preprocessing): ln_m | wconv | wconv_o | pair
// ---------------------------------------------------------------------------
#define PREP_LN  4096
#define PREP_WC  (PREP_LN + 1024)   // 5120
#define PREP_WO  (PREP_WC + 256)    // 5376
#define PREP_TOT (PREP_WO + 8192)   // 13568

__global__ __launch_bounds__(256) void prep_kernel(
    const float* __restrict__ M_raw, const float* __restrict__ mlsc,
    const float* __restrict__ mlbi,
    const float* __restrict__ Wq, const float* __restrict__ Wg,
    const float* __restrict__ Wo,
    const float* __restrict__ Z, const float* __restrict__ zsc,
    const float* __restrict__ zbi, const float* __restrict__ Wb)
{
    __shared__ float swb[1024];
    __shared__ float ssc[128], sbi[128];
    __shared__ float spb[64];

    int b = blockIdx.x;
    int tid = threadIdx.x;

    if (b < PREP_LN) {
        int w = tid >> 5, l = tid & 31;
        int row = b * 8 + w;
        const float4* xr = (const float4*)(M_raw + (size_t)row * 256);
        float4 a = xr[l], bb = xr[l + 32];
        float s1 = (a.x + a.y) + (a.z + a.w) + (bb.x + bb.y) + (bb.z + bb.w);
        float s2 = a.x * a.x + a.y * a.y + a.z * a.z + a.w * a.w
                 + bb.x * bb.x + bb.y * bb.y + bb.z * bb.z + bb.w * bb.w;
        s1 = warp_sum(s1);
        s2 = warp_sum(s2);
        float mu  = s1 * (1.0f / 256.0f);
        float var = s2 * (1.0f / 256.0f) - mu * mu;
        float inv = rsqrtf(var + 1e-5f);

        float4 sa = ((const float4*)mlsc)[l], sb4 = ((const float4*)mlsc)[l + 32];
        float4 ba = ((const float4*)mlbi)[l], bb4 = ((const float4*)mlbi)[l + 32];

        float ya[4] = { (a.x - mu) * inv * sa.x + ba.x, (a.y - mu) * inv * sa.y + ba.y,
                        (a.z - mu) * inv * sa.z + ba.z, (a.w - mu) * inv * sa.w + ba.w };
        float yb[4] = { (bb.x - mu) * inv * sb4.x + bb4.x, (bb.y - mu) * inv * sb4.y + bb4.y,
                        (bb.z - mu) * inv * sb4.z + bb4.z, (bb.w - mu) * inv * sb4.w + bb4.w };

        __nv_bfloat16* mh = g_Mh + (size_t)row * 256;
        __nv_bfloat16* ml = g_Ml + (size_t)row * 256;
#pragma unroll
        for (int g = 0; g < 2; g++) {
            float* y = g ? yb : ya;
            int c = l * 4 + g * 128;
            __nv_bfloat162 h0, h1, l0, l1;
            h0.x = __float2bfloat16(y[0]); h0.y = __float2bfloat16(y[1]);
            h1.x = __float2bfloat16(y[2]); h1.y = __float2bfloat16(y[3]);
            l0.x = __float2bfloat16(y[0] - __bfloat162float(h0.x));
            l0.y = __float2bfloat16(y[1] - __bfloat162float(h0.y));
            l1.x = __float2bfloat16(y[2] - __bfloat162float(h1.x));
            l1.y = __float2bfloat16(y[3] - __bfloat162float(h1.y));
            *(__nv_bfloat162*)(mh + c)     = h0;
            *(__nv_bfloat162*)(mh + c + 2) = h1;
            *(__nv_bfloat162*)(ml + c)     = l0;
            *(__nv_bfloat162*)(ml + c + 2) = l1;
        }
    } else if (b < PREP_WC) {
        int i = (b - PREP_LN) * 256 + tid;
        float v = (i < 768 * 256) ? Wq[i] : Wg[i - 768 * 256];
        __nv_bfloat16 hi = __float2bfloat16(v);
        g_Wh[i] = hi;
        g_Wl[i] = __float2bfloat16(v - __bfloat162float(hi));
    } else if (b < PREP_WO) {
        int i = (b - PREP_WC) * 256 + tid;
        float v = Wo[i];
        __nv_bfloat16 hi = __float2bfloat16(v);
        g_Oh[i] = hi;
        g_Ol[i] = __float2bfloat16(v - __bfloat162float(hi));
    } else {
        int pb = b - PREP_WO;
        if (tid < 128) { ssc[tid] = zsc[tid]; sbi[tid] = zbi[tid]; }
        ((float4*)swb)[tid] = ((const float4*)Wb)[tid];
        __syncthreads();

        int w = tid >> 5, l = tid & 31;
        int row = pb * 8 + w;                // = q*256 + k
        float4 z = ((const float4*)(Z + (size_t)row * 128))[l];
        float s1 = (z.x + z.y) + (z.z + z.w);
        float s2 = z.x * z.x + z.y * z.y + z.z * z.z + z.w * z.w;
        s1 = warp_sum(s1);
        s2 = warp_sum(s2);
        float mu  = s1 * (1.0f / 128.0f);
        float var = s2 * (1.0f / 128.0f) - mu * mu;
        float inv = rsqrtf(var + 1e-5f);
        int c = l * 4;
        float zn0 = (z.x - mu) * inv * ssc[c]     + sbi[c];
        float zn1 = (z.y - mu) * inv * ssc[c + 1] + sbi[c + 1];
        float zn2 = (z.z - mu) * inv * ssc[c + 2] + sbi[c + 2];
        float zn3 = (z.w - mu) * inv * ssc[c + 3] + sbi[c + 3];

        float p[8];
#pragma unroll
        for (int hh = 0; hh < 8; hh++) {
            float4 wb4 = ((const float4*)swb)[hh * 32 + l];
            p[hh] = zn0 * wb4.x + zn1 * wb4.y + zn2 * wb4.z + zn3 * wb4.w;
        }
#pragma unroll
        for (int hh = 0; hh < 8; hh++) p[hh] += __shfl_xor_sync(0xffffffffu, p[hh], 16);
        float q0 = (l & 16) ? p[4] : p[0];
        float q1 = (l & 16) ? p[5] : p[1];
        float q2 = (l & 16) ? p[6] : p[2];
        float q3 = (l & 16) ? p[7] : p[3];
        q0 += __shfl_xor_sync(0xffffffffu, q0, 8);
        q1 += __shfl_xor_sync(0xffffffffu, q1, 8);
        q2 += __shfl_xor_sync(0xffffffffu, q2, 8);
        q3 += __shfl_xor_sync(0xffffffffu, q3, 8);
        float r0 = (l & 8) ? q2 : q0;
        float r1 = (l & 8) ? q3 : q1;
        r0 += __shfl_xor_sync(0xffffffffu, r0, 4);
        r1 += __shfl_xor_sync(0xffffffffu, r1, 4);
        float s0 = (l & 4) ? r1 : r0;
        s0 += __shfl_xor_sync(0xffffffffu, s0, 2);
        s0 += __shfl_xor_sync(0xffffffffu, s0, 1);
        if ((l & 3) == 0) spb[w * 8 + (l >> 2)] = s0 * LOG2E;
        __syncthreads();
        if (tid < 64) {
            int hh = tid >> 3, j = tid & 7;
            int row0 = pb * 8;
            int qq = row0 >> 8, k0 = row0 & 255;
            g_pbB[(size_t)hh * 65536 + qq * 256 + k0 + j] = __float2bfloat16(spb[j * 8 + hh]);
        }
    }
}

// ---------------------------------------------------------------------------
// Kernel 3: projection GEMM (mma.sync bf16, precision-tiered hi/lo).
// ---------------------------------------------------------------------------
#define OFF_AH 0
#define OFF_AL 10240
#define OFF_BH 20480
#define OFF_BL 30720
#define PROJ_STAGE 40960
#define PROJ_SMEM  (2 * PROJ_STAGE)

__global__ __launch_bounds__(256) void gemm_proj_mma()
{
    extern __shared__ __align__(16) unsigned char smb[];
    uint32_t sbase = smem_u32(smb);
    int tid = threadIdx.x;
    int lane = tid & 31, wid = tid >> 5;
    int wm = wid >> 2, wn = wid & 3;
    int bm = blockIdx.y * 128, bn = blockIdx.x * 128;
    int cat = (bn < 512) ? 3 : (bn < 768 ? 2 : 1);

    float acc[4][4][4] = {};

    int lrow = tid >> 1, lhalf = tid & 1;
    size_t gA = (size_t)(bm + lrow) * 256 + lhalf * 16;
    size_t gB = (size_t)(bn + lrow) * 256 + lhalf * 16;
    uint32_t sOff = lrow * 80 + lhalf * 32;

    uint32_t aRow = (lane & 15);
    uint32_t aChunk = (lane >> 4) << 3;
    uint32_t bRow = (lane & 7) + ((lane >> 4) << 3);
    uint32_t bChunk = ((lane >> 3) & 1) << 3;

    {
        uint32_t b = sbase;
        CP16(b + OFF_AH + sOff, g_Mh + gA); CP16(b + OFF_AH + sOff + 16, g_Mh + gA + 8);
        if (cat == 3) {
            CP16(b + OFF_AL + sOff, g_Ml + gA); CP16(b + OFF_AL + sOff + 16, g_Ml + gA + 8);
        }
        CP16(b + OFF_BH + sOff, g_Wh + gB); CP16(b + OFF_BH + sOff + 16, g_Wh + gB + 8);
        if (cat >= 2) {
            CP16(b + OFF_BL + sOff, g_Wl + gB); CP16(b + OFF_BL + sOff + 16, g_Wl + gB + 8);
        }
        CP_COMMIT();
    }

#pragma unroll 1
    for (int t = 0; t < 8; t++) {
        if (t < 7) {
            int c = t + 1;
            uint32_t b = sbase + (c & 1) * PROJ_STAGE;
            const __nv_bfloat16* p;
            p = g_Mh + gA + c * 32;
            CP16(b + OFF_AH + sOff, p); CP16(b + OFF_AH + sOff + 16, p + 8);
            if (cat == 3) {
                p = g_Ml + gA + c * 32;
                CP16(b + OFF_AL + sOff, p); CP16(b + OFF_AL + sOff + 16, p + 8);
            }
            p = g_Wh + gB + c * 32;
            CP16(b + OFF_BH + sOff, p); CP16(b + OFF_BH + sOff + 16, p + 8);
            if (cat >= 2) {
                p = g_Wl + gB + c * 32;
                CP16(b + OFF_BL + sOff, p); CP16(b + OFF_BL + sOff + 16, p + 8);
            }
            CP_COMMIT();
            asm volatile("cp.async.wait_group 1;" ::: "memory");
        } else {
            asm volatile("cp.async.wait_group 0;" ::: "memory");
        }
        __syncthreads();

        uint32_t sb = sbase + (t & 1) * PROJ_STAGE;
#pragma unroll
        for (int ks = 0; ks < 2; ks++) {
            uint32_t ah[4][4], al[4][4], bh[2][4], bl[2][4];
#pragma unroll
            for (int mi = 0; mi < 4; mi++) {
                uint32_t ad = sb + (wm * 64 + mi * 16 + aRow) * 80
                            + (ks * 16 + aChunk) * 2;
                LDM_A(ah[mi], ad + OFF_AH);
                if (cat == 3) LDM_A(al[mi], ad + OFF_AL);
            }
#pragma unroll
            for (int ng = 0; ng < 2; ng++) {
                uint32_t bd = sb + (wn * 32 + ng * 16 + bRow) * 80
                            + (ks * 16 + bChunk) * 2;
                LDM_A(bh[ng], bd + OFF_BH);
                if (cat >= 2) LDM_A(bl[ng], bd + OFF_BL);
            }
#pragma unroll
            for (int mi = 0; mi < 4; mi++) {
#pragma unroll
                for (int nj = 0; nj < 4; nj++) {
                    int ng = nj >> 1, sub = (nj & 1) * 2;
                    MMA_BF16(acc[mi][nj], ah[mi], bh[ng][sub], bh[ng][sub + 1]);
                    if (cat >= 2) MMA_BF16(acc[mi][nj], ah[mi], bl[ng][sub], bl[ng][sub + 1]);
                    if (cat == 3) MMA_BF16(acc[mi][nj], al[mi], bh[ng][sub], bh[ng][sub + 1]);
                }
            }
        }
        __syncthreads();
    }

    int r0 = bm + wm * 64 + (lane >> 2);
    int c0 = bn + wn * 32 + (lane & 3) * 2;
    if (bn < 768) {
        float sc = (bn < 256) ? (0.17677669529663688f * LOG2E) : 1.0f;
#pragma unroll
        for (int mi = 0; mi < 4; mi++) {
#pragma unroll
            for (int nj = 0; nj < 4; nj++) {
                int c = c0 + nj * 8;
#pragma unroll
                for (int p = 0; p < 2; p++) {
                    int r = r0 + mi * 16 + p * 8;
                    float v0 = acc[mi][nj][2 * p] * sc;
                    float v1 = acc[mi][nj][2 * p + 1] * sc;
                    __nv_bfloat16 h0 = __float2bfloat16(v0);
                    __nv_bfloat16 h1 = __float2bfloat16(v1);
                    __nv_bfloat162 hh; hh.x = h0; hh.y = h1;
                    __nv_bfloat162 ll;
                    ll.x = __float2bfloat16(v0 - __bfloat162float(h0));
                    ll.y = __float2bfloat16(v1 - __bfloat162float(h1));
                    *(__nv_bfloat162*)(g_Xh + (size_t)r * 768 + c) = hh;
                    *(__nv_bfloat162*)(g_Xl + (size_t)r * 768 + c) = ll;
                }
            }
        }
    } else {
#pragma unroll
        for (int mi = 0; mi < 4; mi++) {
#pragma unroll
            for (int nj = 0; nj < 4; nj++) {
                int c = c0 + nj * 8 - 768;
#pragma unroll
                for (int p = 0; p < 2; p++) {
                    int r = r0 + mi * 16 + p * 8;
                    *(float2*)(g_gate + (size_t)r * 256 + c) =
                        make_float2(acc[mi][nj][2 * p], acc[mi][nj][2 * p + 1]);
                }
            }
        }
    }
}

// ---------------------------------------------------------------------------
// Kernel 4: flash attention via mma.sync (exp2 softmax); epilogue applies
// sigmoid gate and emits bf16 hi/lo A-operand for the output GEMM.
// ---------------------------------------------------------------------------
#define OQH 0
#define OQL 20480
#define OKH 40960
#define OKL 61440
#define OVH 81920
#define OVL 102400
#define OPB 122880
#define PBSTRIDE 36864
#define OMB 196608
#define ATTN_SMEM 197632

__global__ __launch_bounds__(256) void attn_mma(
    const float* __restrict__ mask, const float* __restrict__ gbias)
{
    extern __shared__ __align__(16) unsigned char smb[];
    uint32_t sb = smem_u32(smb);
    int tid = threadIdx.x;
    int lane = tid & 31, w = tid >> 5;
    int h = blockIdx.x, s = blockIdx.y;

    const __nv_bfloat16* XhB = g_Xh + (size_t)s * 256 * 768;
    const __nv_bfloat16* XlB = g_Xl + (size_t)s * 256 * 768;

#pragma unroll 1
    for (int i = tid; i < 1024; i += 256) {
        int r = i >> 2, seg = i & 3;
        uint32_t d = r * 80 + seg * 16;
        size_t off = (size_t)r * 768 + h * 32 + seg * 8;
        CP16(sb + OQH + d, XhB + off);
        CP16(sb + OQL + d, XlB + off);
        CP16(sb + OKH + d, XhB + off + 256);
        CP16(sb + OKL + d, XlB + off + 256);
        CP16(sb + OVH + d, XhB + off + 512);
        CP16(sb + OVL + d, XlB + off + 512);
    }
    {
        const __nv_bfloat16* pbB = g_pbB + (size_t)h * 65536;
#pragma unroll 1
        for (int i = tid; i < 2048; i += 256) {
            int q = i >> 3, seg = i & 7;
            CP16(sb + OPB + q * 144 + seg * 16, pbB + (size_t)q * 256 + seg * 8);
        }
    }
    CP_COMMIT();
    ((float*)(smb + OMB))[tid] = (1e9f * LOG2E) * (mask[s * 256 + tid] - 1.0f);
    asm volatile("cp.async.wait_group 0;" ::: "memory");
    __syncthreads();

    uint32_t aRow = lane & 15, aChunk = (lane >> 4) << 3;
    uint32_t bRow = (lane & 7) + ((lane >> 4) << 3);
    uint32_t bChunk = ((lane >> 3) & 1) << 3;
    uint32_t vkRow = (lane & 7) + (((lane >> 3) & 1) << 3);
    uint32_t vcCol = (lane >> 4) << 3;

    uint32_t ah[2][2][4], al[2][2][4];
#pragma unroll
    for (int mi = 0; mi < 2; mi++)
#pragma unroll
        for (int ks = 0; ks < 2; ks++) {
            uint32_t ad = sb + (w * 32 + mi * 16 + aRow) * 80 + (ks * 16 + aChunk) * 2;
            LDM_A(ah[mi][ks], ad + OQH);
            LDM_A(al[mi][ks], ad + OQL);
        }

    float o[2][4][4] = {};
    float mrow[4] = {-1e30f, -1e30f, -1e30f, -1e30f};
    float srow[4] = {};

#pragma unroll 1
    for (int kb = 0; kb < 4; kb++) {
        if (kb < 3) {
            const __nv_bfloat16* pbB = g_pbB + (size_t)h * 65536 + (kb + 1) * 64;
            uint32_t dst = sb + OPB + ((kb + 1) & 1) * PBSTRIDE;
#pragma unroll 1
            for (int i = tid; i < 2048; i += 256) {
                int q = i >> 3, seg = i & 7;
                CP16(dst + q * 144 + seg * 16, pbB + (size_t)q * 256 + seg * 8);
            }
            CP_COMMIT();
            asm volatile("cp.async.wait_group 1;" ::: "memory");
        } else {
            asm volatile("cp.async.wait_group 0;" ::: "memory");
        }
        __syncthreads();

        float sfr[2][8][4] = {};
#pragma unroll
        for (int ks = 0; ks < 2; ks++)
#pragma unroll
            for (int ng = 0; ng < 4; ng++) {
                uint32_t kh[4], kl[4];
                uint32_t bd = sb + (kb * 64 + ng * 16 + bRow) * 80
                            + (ks * 16 + bChunk) * 2;
                LDM_A(kh, bd + OKH);
                LDM_A(kl, bd + OKL);
#pragma unroll
                for (int mi = 0; mi < 2; mi++) {
                    MMA_BF16(sfr[mi][ng * 2], ah[mi][ks], kh[0], kh[1]);
                    MMA_BF16(sfr[mi][ng * 2], ah[mi][ks], kl[0], kl[1]);
                    MMA_BF16(sfr[mi][ng * 2], al[mi][ks], kh[0], kh[1]);
                    MMA_BF16(sfr[mi][ng * 2 + 1], ah[mi][ks], kh[2], kh[3]);
                    MMA_BF16(sfr[mi][ng * 2 + 1], ah[mi][ks], kl[2], kl[3]);
                    MMA_BF16(sfr[mi][ng * 2 + 1], al[mi][ks], kh[2], kh[3]);
                }
            }

        uint32_t pbuf = sb + OPB + (kb & 1) * PBSTRIDE;
        const float* mbp = (const float*)(smb + OMB) + kb * 64;
#pragma unroll
        for (int mi = 0; mi < 2; mi++) {
            int q0 = w * 32 + mi * 16 + (lane >> 2);
#pragma unroll
            for (int nj = 0; nj < 8; nj++) {
                int cB = nj * 8 + (lane & 3) * 2;
                float2 mv = *(const float2*)(mbp + cB);
                uint32_t u0, u1;
                asm("ld.shared.b32 %0, [%1];" : "=r"(u0) : "r"(pbuf + q0 * 144 + cB * 2));
                asm("ld.shared.b32 %0, [%1];" : "=r"(u1) : "r"(pbuf + (q0 + 8) * 144 + cB * 2));
                float2 p0 = bfu2f2(u0), p1 = bfu2f2(u1);
                sfr[mi][nj][0] += mv.x + p0.x;
                sfr[mi][nj][1] += mv.y + p0.y;
                sfr[mi][nj][2] += mv.x + p1.x;
                sfr[mi][nj][3] += mv.y + p1.y;
            }
        }

#pragma unroll
        for (int mi = 0; mi < 2; mi++)
#pragma unroll
            for (int p = 0; p < 2; p++) {
                int id = mi * 2 + p;
                float mx = mrow[id];
#pragma unroll
                for (int nj = 0; nj < 8; nj++)
                    mx = fmaxf(mx, fmaxf(sfr[mi][nj][2 * p], sfr[mi][nj][2 * p + 1]));
                mx = fmaxf(mx, __shfl_xor_sync(0xffffffffu, mx, 1));
                mx = fmaxf(mx, __shfl_xor_sync(0xffffffffu, mx, 2));
                float es = ex2(mrow[id] - mx);
                mrow[id] = mx;
                float ls = 0.f;
#pragma unroll
                for (int nj = 0; nj < 8; nj++) {
                    float v0 = ex2(sfr[mi][nj][2 * p] - mx);
                    float v1 = ex2(sfr[mi][nj][2 * p + 1] - mx);
                    sfr[mi][nj][2 * p] = v0;
                    sfr[mi][nj][2 * p + 1] = v1;
                    ls += v0 + v1;
                }
                ls += __shfl_xor_sync(0xffffffffu, ls, 1);
                ls += __shfl_xor_sync(0xffffffffu, ls, 2);
                srow[id] = srow[id] * es + ls;
#pragma unroll
                for (int nc = 0; nc < 4; nc++) {
                    o[mi][nc][2 * p] *= es;
                    o[mi][nc][2 * p + 1] *= es;
                }
            }

#pragma unroll
        for (int t = 0; t < 4; t++) {
            uint32_t pa[2][4];
#pragma unroll
            for (int mi = 0; mi < 2; mi++) {
                pa[mi][0] = pk2(sfr[mi][2 * t][0], sfr[mi][2 * t][1]);
                pa[mi][1] = pk2(sfr[mi][2 * t][2], sfr[mi][2 * t][3]);
                pa[mi][2] = pk2(sfr[mi][2 * t + 1][0], sfr[mi][2 * t + 1][1]);
                pa[mi][3] = pk2(sfr[mi][2 * t + 1][2], sfr[mi][2 * t + 1][3]);
            }
#pragma unroll
            for (int ng = 0; ng < 2; ng++) {
                uint32_t vh[4], vl[4];
                uint32_t vd = (kb * 64 + t * 16 + vkRow) * 80 + (ng * 16 + vcCol) * 2;
                LDM_T(vh, sb + OVH + vd);
                LDM_T(vl, sb + OVL + vd);
#pragma unroll
                for (int mi = 0; mi < 2; mi++) {
                    MMA_BF16(o[mi][ng * 2], pa[mi], vh[0], vh[1]);
                    MMA_BF16(o[mi][ng * 2], pa[mi], vl[0], vl[1]);
                    MMA_BF16(o[mi][ng * 2 + 1], pa[mi], vh[2], vh[3]);
                    MMA_BF16(o[mi][ng * 2 + 1], pa[mi], vl[2], vl[3]);
                }
            }
        }
        __syncthreads();
    }

    // epilogue: normalize, apply sigmoid gate, emit bf16 hi/lo
#pragma unroll
    for (int mi = 0; mi < 2; mi++)
#pragma unroll
        for (int p = 0; p < 2; p++) {
            float inv = 1.0f / srow[mi * 2 + p];
            int r = s * 256 + w * 32 + mi * 16 + (lane >> 2) + p * 8;
#pragma unroll
            for (int nc = 0; nc < 4; nc++) {
                int c = h * 32 + nc * 8 + (lane & 3) * 2;
                float2 gl = *(const float2*)(g_gate + (size_t)r * 256 + c);
                float2 gb = *(const float2*)(gbias + c);
                float a0 = (o[mi][nc][2 * p] * inv) / (1.0f + __expf(-(gl.x + gb.x)));
                float a1 = (o[mi][nc][2 * p + 1] * inv) / (1.0f + __expf(-(gl.y + gb.y)));
                __nv_bfloat162 hh, ll;
                hh.x = __float2bfloat16(a0);
                hh.y = __float2bfloat16(a1);
                ll.x = __float2bfloat16(a0 - __bfloat162float(hh.x));
                ll.y = __float2bfloat16(a1 - __bfloat162float(hh.y));
                *(__nv_bfloat162*)(g_Ah + (size_t)r * 256 + c) = hh;
                *(__nv_bfloat162*)(g_Al + (size_t)r * 256 + c) = ll;
            }
        }
}

// ---------------------------------------------------------------------------
// Kernel 5: out = A @ W_o^T + M_raw + out_bias (pure pipelined bf16 GEMM,
// A = gated attention output, pre-split hi/lo by attn epilogue).
// ---------------------------------------------------------------------------
__global__ __launch_bounds__(256) void gemm_out_mma(
    const float* __restrict__ Mraw, const float* __restrict__ obias,
    float* __restrict__ out)
{
    extern __shared__ __align__(16) unsigned char smb[];
    uint32_t sbase = smem_u32(smb);
    int tid = threadIdx.x;
    int lane = tid & 31, wid = tid >> 5;
    int wm = wid >> 2, wn = wid & 3;
    int bm = blockIdx.y * 128, bn = blockIdx.x * 128;

    float acc[4][4][4] = {};

    int lrow = tid >> 1, lhalf = tid & 1;
    size_t gA = (size_t)(bm + lrow) * 256 + lhalf * 16;
    size_t gB = (size_t)(bn + lrow) * 256 + lhalf * 16;
    uint32_t sOff = lrow * 80 + lhalf * 32;

    uint32_t aRow = (lane & 15);
    uint32_t aChunk = (lane >> 4) << 3;
    uint32_t bRow = (lane & 7) + ((lane >> 4) << 3);
    uint32_t bChunk = ((lane >> 3) & 1) << 3;

    {
        uint32_t b = sbase;
        CP16(b + OFF_AH + sOff, g_Ah + gA); CP16(b + OFF_AH + sOff + 16, g_Ah + gA + 8);
        CP16(b + OFF_AL + sOff, g_Al + gA); CP16(b + OFF_AL + sOff + 16, g_Al + gA + 8);
        CP16(b + OFF_BH + sOff, g_Oh + gB); CP16(b + OFF_BH + sOff + 16, g_Oh + gB + 8);
        CP16(b + OFF_BL + sOff, g_Ol + gB); CP16(b + OFF_BL + sOff + 16, g_Ol + gB + 8);
        CP_COMMIT();
    }

#pragma unroll 1
    for (int t = 0; t < 8; t++) {
        if (t < 7) {
            int c = t + 1;
            uint32_t b = sbase + (c & 1) * PROJ_STAGE;
            const __nv_bfloat16* p;
            p = g_Ah + gA + c * 32;
            CP16(b + OFF_AH + sOff, p); CP16(b + OFF_AH + sOff + 16, p + 8);
            p = g_Al + gA + c * 32;
            CP16(b + OFF_AL + sOff, p); CP16(b + OFF_AL + sOff + 16, p + 8);
            p = g_Oh + gB + c * 32;
            CP16(b + OFF_BH + sOff, p); CP16(b + OFF_BH + sOff + 16, p + 8);
            p = g_Ol + gB + c * 32;
            CP16(b + OFF_BL + sOff, p); CP16(b + OFF_BL + sOff + 16, p + 8);
            CP_COMMIT();
            asm volatile("cp.async.wait_group 1;" ::: "memory");
        } else {
            asm volatile("cp.async.wait_group 0;" ::: "memory");
        }
        __syncthreads();

        uint32_t sb = sbase + (t & 1) * PROJ_STAGE;
#pragma unroll
        for (int ks = 0; ks < 2; ks++) {
            uint32_t ah[4][4], al[4][4], bh[2][4], bl[2][4];
#pragma unroll
            for (int mi = 0; mi < 4; mi++) {
                uint32_t ad = sb + (wm * 64 + mi * 16 + aRow) * 80
                            + (ks * 16 + aChunk) * 2;
                LDM_A(ah[mi], ad + OFF_AH);
                LDM_A(al[mi], ad + OFF_AL);
            }
#pragma unroll
            for (int ng = 0; ng < 2; ng++) {
                uint32_t bd = sb + (wn * 32 + ng * 16 + bRow) * 80
                            + (ks * 16 + bChunk) * 2;
                LDM_A(bh[ng], bd + OFF_BH);
                LDM_A(bl[ng], bd + OFF_BL);
            }
#pragma unroll
            for (int mi = 0; mi < 4; mi++) {
#pragma unroll
                for (int nj = 0; nj < 4; nj++) {
                    int ng = nj >> 1, sub = (nj & 1) * 2;
                    MMA_BF16(acc[mi][nj], ah[mi], bh[ng][sub], bh[ng][sub + 1]);
                    MMA_BF16(acc[mi][nj], ah[mi], bl[ng][sub], bl[ng][sub + 1]);
                    MMA_BF16(acc[mi][nj], al[mi], bh[ng][sub], bh[ng][sub + 1]);
                }
            }
        }
        __syncthreads();
    }

    int r0 = bm + wm * 64 + (lane >> 2);
    int c0 = bn + wn * 32 + (lane & 3) * 2;
#pragma unroll
    for (int mi = 0; mi < 4; mi++) {
#pragma unroll
        for (int nj = 0; nj < 4; nj++) {
            int r = r0 + mi * 16, c = c0 + nj * 8;
            float ob0 = obias[c], ob1 = obias[c + 1];
            float2 m0 = *(const float2*)(Mraw + (size_t)r * 256 + c);
            *(float2*)(out + (size_t)r * 256 + c) =
                make_float2(acc[mi][nj][0] + m0.x + ob0, acc[mi][nj][1] + m0.y + ob1);
            float2 m1 = *(const float2*)(Mraw + (size_t)(r + 8) * 256 + c);
            *(float2*)(out + (size_t)(r + 8) * 256 + c) =
                make_float2(acc[mi][nj][2] + m1.x + ob0, acc[mi][nj][3] + m1.y + ob1);
        }
    }
}

// ---------------------------------------------------------------------------
extern "C" void kernel_launch(void* const* d_in, const int* in_sizes, int n_in,
                              void* d_out, int out_size)
{
    const float* M_raw      = (const float*)d_in[0];
    const float* Z          = (const float*)d_in[1];
    const float* M_mask     = (const float*)d_in[2];
    const float* ln_m_scale = (const float*)d_in[3];
    const float* ln_m_bias  = (const float*)d_in[4];
    const float* ln_z_scale = (const float*)d_in[5];
    const float* ln_z_bias  = (const float*)d_in[6];
    const float* W_b        = (const float*)d_in[7];
    const float* W_qkv      = (const float*)d_in[8];
    const float* W_gate     = (const float*)d_in[9];
    const float* gbias      = (const float*)d_in[10];
    const float* W_o        = (const float*)d_in[11];
    const float* out_bias   = (const float*)d_in[12];
    float* out = (float*)d_out;

    cudaFuncSetAttribute(gemm_proj_mma, cudaFuncAttributeMaxDynamicSharedMemorySize,
                         PROJ_SMEM);
    cudaFuncSetAttribute(attn_mma, cudaFuncAttributeMaxDynamicSharedMemorySize,
                         ATTN_SMEM);
    cudaFuncSetAttribute(gemm_out_mma, cudaFuncAttributeMaxDynamicSharedMemorySize,
                         PROJ_SMEM);

    prep_kernel<<<PREP_TOT, 256>>>(M_raw, ln_m_scale, ln_m_bias,
                                   W_qkv, W_gate, W_o,
                                   Z, ln_z_scale, ln_z_bias, W_b);
    gemm_proj_mma<<<dim3(EPROJ / 128, NROWS / 128), 256, PROJ_SMEM>>>();
    attn_mma<<<dim3(NHEAD, NSEQ), 256, ATTN_SMEM>>>(M_mask, gbias);
    gemm_out_mma<<<dim3(256 / 128, NROWS / 128), 256, PROJ_SMEM>>>(M_raw, out_bias, out);
}

// round 9
// speedup vs baseline: 1.0044x; 1.0044x over previous
#include <cuda_runtime.h>
#include <cuda_bf16.h>
#include <cstdint>
#include <math.h>

// Problem constants
#define D_NODE 256
#define D_PAIR 128
#define NHEAD  8
#define NSEQ   128
#define NRES   256
#define NROWS  (NSEQ * NRES)          // 32768
#define EPROJ  1024                    // 768 qkv + 256 gate

#define LOG2E 1.4426950408889634f

// Scratch
__device__ __nv_bfloat16 g_Mh[(size_t)NROWS * D_NODE];   // LN(M) hi
__device__ __nv_bfloat16 g_Ml[(size_t)NROWS * D_NODE];   // LN(M) lo
__device__ __nv_bfloat16 g_Wh[(size_t)EPROJ * D_NODE];   // [Wqkv;Wgate] hi
__device__ __nv_bfloat16 g_Wl[(size_t)EPROJ * D_NODE];   // lo
__device__ __nv_bfloat16 g_Oh[(size_t)D_NODE * D_NODE];  // W_o hi
__device__ __nv_bfloat16 g_Ol[(size_t)D_NODE * D_NODE];  // W_o lo
__device__ __nv_bfloat16 g_Xh[(size_t)NROWS * 768];      // q(scaled)|k|v hi
__device__ __nv_bfloat16 g_Xl[(size_t)NROWS * 768];      // lo
__device__ float         g_gate[(size_t)NROWS * 256];    // gate logits fp32
__device__ __nv_bfloat16 g_pbB[(size_t)NHEAD * NRES * NRES]; // pair bias*log2e [h][q][k]
__device__ __nv_bfloat16 g_Ah[(size_t)NROWS * D_NODE];   // gated attn out hi
__device__ __nv_bfloat16 g_Al[(size_t)NROWS * D_NODE];   // gated attn out lo

__device__ __forceinline__ uint32_t smem_u32(const void* p) {
    uint32_t a;
    asm("{ .reg .u64 t; cvta.to.shared.u64 t, %1; cvt.u32.u64 %0, t; }"
        : "=r"(a) : "l"(p));
    return a;
}

#define LDM_X4(r0, r1, r2, r3, addr)                                           \
    asm volatile("ldmatrix.sync.aligned.m8n8.x4.shared.b16 {%0,%1,%2,%3}, [%4];" \
                 : "=r"(r0), "=r"(r1), "=r"(r2), "=r"(r3) : "r"(addr))
#define LDM_A(v, addr) LDM_X4((v)[0], (v)[1], (v)[2], (v)[3], addr)

#define LDM_T(v, addr)                                                         \
    asm volatile("ldmatrix.sync.aligned.m8n8.x4.trans.shared.b16 {%0,%1,%2,%3}, [%4];" \
                 : "=r"((v)[0]), "=r"((v)[1]), "=r"((v)[2]), "=r"((v)[3]) : "r"(addr))

#define MMA_BF16(d, a, b0, b1)                                                 \
    asm volatile("mma.sync.aligned.m16n8k16.row.col.f32.bf16.bf16.f32 "        \
                 "{%0,%1,%2,%3}, {%4,%5,%6,%7}, {%8,%9}, {%0,%1,%2,%3};"       \
                 : "+f"((d)[0]), "+f"((d)[1]), "+f"((d)[2]), "+f"((d)[3])      \
                 : "r"((a)[0]), "r"((a)[1]), "r"((a)[2]), "r"((a)[3]),         \
                   "r"(b0), "r"(b1))

#define CP16(s, g)                                                             \
    asm volatile("cp.async.cg.shared.global [%0], [%1], 16;" :: "r"(s), "l"(g))
#define CP_COMMIT() asm volatile("cp.async.commit_group;" ::: "memory")

__device__ __forceinline__ uint32_t pk2(float lo, float hi) {
    uint32_t d;
    asm("cvt.rn.bf16x2.f32 %0, %1, %2;" : "=r"(d) : "f"(hi), "f"(lo));
    return d;
}
__device__ __forceinline__ float2 bfu2f2(uint32_t u) {
    __nv_bfloat162 b = *reinterpret_cast<__nv_bfloat162*>(&u);
    return make_float2(__bfloat162float(b.x), __bfloat162float(b.y));
}
__device__ __forceinline__ float ex2(float x) {
    float r;
    asm("ex2.approx.f32 %0, %1;" : "=f"(r) : "f"(x));
    return r;
}

__device__ __forceinline__ float warp_sum(float v) {
#pragma unroll
    for (int o = 16; o > 0; o >>= 1) v += __shfl_xor_sync(0xffffffffu, v, o);
    return v;
}

// ---------------------------------------------------------------------------
// Kernel 1 (fused preprocessing): ln_m | wconv | wconv_o | pair
// ---------------------------------------------------------------------------
#define PREP_LN  4096
#define PREP_WC  (PREP_LN + 1024)   // 5120
#define PREP_WO  (PREP_WC + 256)    // 5376
#define PREP_TOT (PREP_WO + 8192)   // 13568

__global__ __launch_bounds__(256) void prep_kernel(
    const float* __restrict__ M_raw, const float* __restrict__ mlsc,
    const float* __restrict__ mlbi,
    const float* __restrict__ Wq, const float* __restrict__ Wg,
    const float* __restrict__ Wo,
    const float* __restrict__ Z, const float* __restrict__ zsc,
    const float* __restrict__ zbi, const float* __restrict__ Wb)
{
    __shared__ float swb[1024];
    __shared__ float ssc[128], sbi[128];
    __shared__ float spb[64];

    int b = blockIdx.x;
    int tid = threadIdx.x;

    if (b < PREP_LN) {
        int w = tid >> 5, l = tid & 31;
        int row = b * 8 + w;
        const float4* xr = (const float4*)(M_raw + (size_t)row * 256);
        float4 a = xr[l], bb = xr[l + 32];
        float s1 = (a.x + a.y) + (a.z + a.w) + (bb.x + bb.y) + (bb.z + bb.w);
        float s2 = a.x * a.x + a.y * a.y + a.z * a.z + a.w * a.w
                 + bb.x * bb.x + bb.y * bb.y + bb.z * bb.z + bb.w * bb.w;
        s1 = warp_sum(s1);
        s2 = warp_sum(s2);
        float mu  = s1 * (1.0f / 256.0f);
        float var = s2 * (1.0f / 256.0f) - mu * mu;
        float inv = rsqrtf(var + 1e-5f);

        float4 sa = ((const float4*)mlsc)[l], sb4 = ((const float4*)mlsc)[l + 32];
        float4 ba = ((const float4*)mlbi)[l], bb4 = ((const float4*)mlbi)[l + 32];

        float ya[4] = { (a.x - mu) * inv * sa.x + ba.x, (a.y - mu) * inv * sa.y + ba.y,
                        (a.z - mu) * inv * sa.z + ba.z, (a.w - mu) * inv * sa.w + ba.w };
        float yb[4] = { (bb.x - mu) * inv * sb4.x + bb4.x, (bb.y - mu) * inv * sb4.y + bb4.y,
                        (bb.z - mu) * inv * sb4.z + bb4.z, (bb.w - mu) * inv * sb4.w + bb4.w };

        __nv_bfloat16* mh = g_Mh + (size_t)row * 256;
        __nv_bfloat16* ml = g_Ml + (size_t)row * 256;
#pragma unroll
        for (int g = 0; g < 2; g++) {
            float* y = g ? yb : ya;
            int c = l * 4 + g * 128;
            __nv_bfloat162 h0, h1, l0, l1;
            h0.x = __float2bfloat16(y[0]); h0.y = __float2bfloat16(y[1]);
            h1.x = __float2bfloat16(y[2]); h1.y = __float2bfloat16(y[3]);
            l0.x = __float2bfloat16(y[0] - __bfloat162float(h0.x));
            l0.y = __float2bfloat16(y[1] - __bfloat162float(h0.y));
            l1.x = __float2bfloat16(y[2] - __bfloat162float(h1.x));
            l1.y = __float2bfloat16(y[3] - __bfloat162float(h1.y));
            *(__nv_bfloat162*)(mh + c)     = h0;
            *(__nv_bfloat162*)(mh + c + 2) = h1;
            *(__nv_bfloat162*)(ml + c)     = l0;
            *(__nv_bfloat162*)(ml + c + 2) = l1;
        }
    } else if (b < PREP_WC) {
        int i = (b - PREP_LN) * 256 + tid;
        float v = (i < 768 * 256) ? Wq[i] : Wg[i - 768 * 256];
        __nv_bfloat16 hi = __float2bfloat16(v);
        g_Wh[i] = hi;
        g_Wl[i] = __float2bfloat16(v - __bfloat162float(hi));
    } else if (b < PREP_WO) {
        int i = (b - PREP_WC) * 256 + tid;
        float v = Wo[i];
        __nv_bfloat16 hi = __float2bfloat16(v);
        g_Oh[i] = hi;
        g_Ol[i] = __float2bfloat16(v - __bfloat162float(hi));
    } else {
        int pb = b - PREP_WO;
        if (tid < 128) { ssc[tid] = zsc[tid]; sbi[tid] = zbi[tid]; }
        ((float4*)swb)[tid] = ((const float4*)Wb)[tid];
        __syncthreads();

        int w = tid >> 5, l = tid & 31;
        int row = pb * 8 + w;                // = q*256 + k
        float4 z = ((const float4*)(Z + (size_t)row * 128))[l];
        float s1 = (z.x + z.y) + (z.z + z.w);
        float s2 = z.x * z.x + z.y * z.y + z.z * z.z + z.w * z.w;
        s1 = warp_sum(s1);
        s2 = warp_sum(s2);
        float mu  = s1 * (1.0f / 128.0f);
        float var = s2 * (1.0f / 128.0f) - mu * mu;
        float inv = rsqrtf(var + 1e-5f);
        int c = l * 4;
        float zn0 = (z.x - mu) * inv * ssc[c]     + sbi[c];
        float zn1 = (z.y - mu) * inv * ssc[c + 1] + sbi[c + 1];
        float zn2 = (z.z - mu) * inv * ssc[c + 2] + sbi[c + 2];
        float zn3 = (z.w - mu) * inv * ssc[c + 3] + sbi[c + 3];

        float p[8];
#pragma unroll
        for (int hh = 0; hh < 8; hh++) {
            float4 wb4 = ((const float4*)swb)[hh * 32 + l];
            p[hh] = zn0 * wb4.x + zn1 * wb4.y + zn2 * wb4.z + zn3 * wb4.w;
        }
#pragma unroll
        for (int hh = 0; hh < 8; hh++) p[hh] += __shfl_xor_sync(0xffffffffu, p[hh], 16);
        float q0 = (l & 16) ? p[4] : p[0];
        float q1 = (l & 16) ? p[5] : p[1];
        float q2 = (l & 16) ? p[6] : p[2];
        float q3 = (l & 16) ? p[7] : p[3];
        q0 += __shfl_xor_sync(0xffffffffu, q0, 8);
        q1 += __shfl_xor_sync(0xffffffffu, q1, 8);
        q2 += __shfl_xor_sync(0xffffffffu, q2, 8);
        q3 += __shfl_xor_sync(0xffffffffu, q3, 8);
        float r0 = (l & 8) ? q2 : q0;
        float r1 = (l & 8) ? q3 : q1;
        r0 += __shfl_xor_sync(0xffffffffu, r0, 4);
        r1 += __shfl_xor_sync(0xffffffffu, r1, 4);
        float s0 = (l & 4) ? r1 : r0;
        s0 += __shfl_xor_sync(0xffffffffu, s0, 2);
        s0 += __shfl_xor_sync(0xffffffffu, s0, 1);
        if ((l & 3) == 0) spb[w * 8 + (l >> 2)] = s0 * LOG2E;
        __syncthreads();
        if (tid < 64) {
            int hh = tid >> 3, j = tid & 7;
            int row0 = pb * 8;
            int qq = row0 >> 8, k0 = row0 & 255;
            g_pbB[(size_t)hh * 65536 + qq * 256 + k0 + j] = __float2bfloat16(spb[j * 8 + hh]);
        }
    }
}

// ---------------------------------------------------------------------------
// Kernel 3: projection GEMM (mma.sync bf16, precision-tiered hi/lo).
// ---------------------------------------------------------------------------
#define OFF_AH 0
#define OFF_AL 10240
#define OFF_BH 20480
#define OFF_BL 30720
#define PROJ_STAGE 40960
#define PROJ_SMEM  (2 * PROJ_STAGE)

__global__ __launch_bounds__(256) void gemm_proj_mma()
{
    extern __shared__ __align__(16) unsigned char smb[];
    uint32_t sbase = smem_u32(smb);
    int tid = threadIdx.x;
    int lane = tid & 31, wid = tid >> 5;
    int wm = wid >> 2, wn = wid & 3;
    int bm = blockIdx.y * 128, bn = blockIdx.x * 128;
    int cat = (bn < 512) ? 3 : (bn < 768 ? 2 : 1);

    float acc[4][4][4] = {};

    int lrow = tid >> 1, lhalf = tid & 1;
    size_t gA = (size_t)(bm + lrow) * 256 + lhalf * 16;
    size_t gB = (size_t)(bn + lrow) * 256 + lhalf * 16;
    uint32_t sOff = lrow * 80 + lhalf * 32;

    uint32_t aRow = (lane & 15);
    uint32_t aChunk = (lane >> 4) << 3;
    uint32_t bRow = (lane & 7) + ((lane >> 4) << 3);
    uint32_t bChunk = ((lane >> 3) & 1) << 3;

    {
        uint32_t b = sbase;
        CP16(b + OFF_AH + sOff, g_Mh + gA); CP16(b + OFF_AH + sOff + 16, g_Mh + gA + 8);
        if (cat == 3) {
            CP16(b + OFF_AL + sOff, g_Ml + gA); CP16(b + OFF_AL + sOff + 16, g_Ml + gA + 8);
        }
        CP16(b + OFF_BH + sOff, g_Wh + gB); CP16(b + OFF_BH + sOff + 16, g_Wh + gB + 8);
        if (cat >= 2) {
            CP16(b + OFF_BL + sOff, g_Wl + gB); CP16(b + OFF_BL + sOff + 16, g_Wl + gB + 8);
        }
        CP_COMMIT();
    }

#pragma unroll 1
    for (int t = 0; t < 8; t++) {
        if (t < 7) {
            int c = t + 1;
            uint32_t b = sbase + (c & 1) * PROJ_STAGE;
            const __nv_bfloat16* p;
            p = g_Mh + gA + c * 32;
            CP16(b + OFF_AH + sOff, p); CP16(b + OFF_AH + sOff + 16, p + 8);
            if (cat == 3) {
                p = g_Ml + gA + c * 32;
                CP16(b + OFF_AL + sOff, p); CP16(b + OFF_AL + sOff + 16, p + 8);
            }
            p = g_Wh + gB + c * 32;
            CP16(b + OFF_BH + sOff, p); CP16(b + OFF_BH + sOff + 16, p + 8);
            if (cat >= 2) {
                p = g_Wl + gB + c * 32;
                CP16(b + OFF_BL + sOff, p); CP16(b + OFF_BL + sOff + 16, p + 8);
            }
            CP_COMMIT();
            asm volatile("cp.async.wait_group 1;" ::: "memory");
        } else {
            asm volatile("cp.async.wait_group 0;" ::: "memory");
        }
        __syncthreads();

        uint32_t sb = sbase + (t & 1) * PROJ_STAGE;
#pragma unroll
        for (int ks = 0; ks < 2; ks++) {
            uint32_t ah[4][4], al[4][4], bh[2][4], bl[2][4];
#pragma unroll
            for (int mi = 0; mi < 4; mi++) {
                uint32_t ad = sb + (wm * 64 + mi * 16 + aRow) * 80
                            + (ks * 16 + aChunk) * 2;
                LDM_A(ah[mi], ad + OFF_AH);
                if (cat == 3) LDM_A(al[mi], ad + OFF_AL);
            }
#pragma unroll
            for (int ng = 0; ng < 2; ng++) {
                uint32_t bd = sb + (wn * 32 + ng * 16 + bRow) * 80
                            + (ks * 16 + bChunk) * 2;
                LDM_A(bh[ng], bd + OFF_BH);
                if (cat >= 2) LDM_A(bl[ng], bd + OFF_BL);
            }
#pragma unroll
            for (int mi = 0; mi < 4; mi++) {
#pragma unroll
                for (int nj = 0; nj < 4; nj++) {
                    int ng = nj >> 1, sub = (nj & 1) * 2;
                    MMA_BF16(acc[mi][nj], ah[mi], bh[ng][sub], bh[ng][sub + 1]);
                    if (cat >= 2) MMA_BF16(acc[mi][nj], ah[mi], bl[ng][sub], bl[ng][sub + 1]);
                    if (cat == 3) MMA_BF16(acc[mi][nj], al[mi], bh[ng][sub], bh[ng][sub + 1]);
                }
            }
        }
        __syncthreads();
    }

    int r0 = bm + wm * 64 + (lane >> 2);
    int c0 = bn + wn * 32 + (lane & 3) * 2;
    if (bn < 768) {
        float sc = (bn < 256) ? (0.17677669529663688f * LOG2E) : 1.0f;
#pragma unroll
        for (int mi = 0; mi < 4; mi++) {
#pragma unroll
            for (int nj = 0; nj < 4; nj++) {
                int c = c0 + nj * 8;
#pragma unroll
                for (int p = 0; p < 2; p++) {
                    int r = r0 + mi * 16 + p * 8;
                    float v0 = acc[mi][nj][2 * p] * sc;
                    float v1 = acc[mi][nj][2 * p + 1] * sc;
                    __nv_bfloat16 h0 = __float2bfloat16(v0);
                    __nv_bfloat16 h1 = __float2bfloat16(v1);
                    __nv_bfloat162 hh; hh.x = h0; hh.y = h1;
                    __nv_bfloat162 ll;
                    ll.x = __float2bfloat16(v0 - __bfloat162float(h0));
                    ll.y = __float2bfloat16(v1 - __bfloat162float(h1));
                    *(__nv_bfloat162*)(g_Xh + (size_t)r * 768 + c) = hh;
                    *(__nv_bfloat162*)(g_Xl + (size_t)r * 768 + c) = ll;
                }
            }
        }
    } else {
#pragma unroll
        for (int mi = 0; mi < 4; mi++) {
#pragma unroll
            for (int nj = 0; nj < 4; nj++) {
                int c = c0 + nj * 8 - 768;
#pragma unroll
                for (int p = 0; p < 2; p++) {
                    int r = r0 + mi * 16 + p * 8;
                    *(float2*)(g_gate + (size_t)r * 256 + c) =
                        make_float2(acc[mi][nj][2 * p], acc[mi][nj][2 * p + 1]);
                }
            }
        }
    }
}

// ---------------------------------------------------------------------------
// Kernel 4: flash attention via mma.sync (exp2 softmax); epilogue stages O in
// smem then does a COALESCED gated write-out of bf16 hi/lo A-operands.
// ---------------------------------------------------------------------------
#define OQH 0
#define OQL 20480
#define OKH 40960
#define OKL 61440
#define OVH 81920
#define OVL 102400
#define OPB 122880
#define PBSTRIDE 36864
#define OMB 196608
#define ATTN_SMEM 197632

__global__ __launch_bounds__(256) void attn_mma(
    const float* __restrict__ mask, const float* __restrict__ gbias)
{
    extern __shared__ __align__(16) unsigned char smb[];
    uint32_t sb = smem_u32(smb);
    int tid = threadIdx.x;
    int lane = tid & 31, w = tid >> 5;
    int h = blockIdx.x, s = blockIdx.y;

    const __nv_bfloat16* XhB = g_Xh + (size_t)s * 256 * 768;
    const __nv_bfloat16* XlB = g_Xl + (size_t)s * 256 * 768;

#pragma unroll 1
    for (int i = tid; i < 1024; i += 256) {
        int r = i >> 2, seg = i & 3;
        uint32_t d = r * 80 + seg * 16;
        size_t off = (size_t)r * 768 + h * 32 + seg * 8;
        CP16(sb + OQH + d, XhB + off);
        CP16(sb + OQL + d, XlB + off);
        CP16(sb + OKH + d, XhB + off + 256);
        CP16(sb + OKL + d, XlB + off + 256);
        CP16(sb + OVH + d, XhB + off + 512);
        CP16(sb + OVL + d, XlB + off + 512);
    }
    {
        const __nv_bfloat16* pbB = g_pbB + (size_t)h * 65536;
#pragma unroll 1
        for (int i = tid; i < 2048; i += 256) {
            int q = i >> 3, seg = i & 7;
            CP16(sb + OPB + q * 144 + seg * 16, pbB + (size_t)q * 256 + seg * 8);
        }
    }
    CP_COMMIT();
    ((float*)(smb + OMB))[tid] = (1e9f * LOG2E) * (mask[s * 256 + tid] - 1.0f);
    asm volatile("cp.async.wait_group 0;" ::: "memory");
    __syncthreads();

    uint32_t aRow = lane & 15, aChunk = (lane >> 4) << 3;
    uint32_t bRow = (lane & 7) + ((lane >> 4) << 3);
    uint32_t bChunk = ((lane >> 3) & 1) << 3;
    uint32_t vkRow = (lane & 7) + (((lane >> 3) & 1) << 3);
    uint32_t vcCol = (lane >> 4) << 3;

    uint32_t ah[2][2][4], al[2][2][4];
#pragma unroll
    for (int mi = 0; mi < 2; mi++)
#pragma unroll
        for (int ks = 0; ks < 2; ks++) {
            uint32_t ad = sb + (w * 32 + mi * 16 + aRow) * 80 + (ks * 16 + aChunk) * 2;
            LDM_A(ah[mi][ks], ad + OQH);
            LDM_A(al[mi][ks], ad + OQL);
        }

    float o[2][4][4] = {};
    float mrow[4] = {-1e30f, -1e30f, -1e30f, -1e30f};
    float srow[4] = {};

#pragma unroll 1
    for (int kb = 0; kb < 4; kb++) {
        if (kb < 3) {
            const __nv_bfloat16* pbB = g_pbB + (size_t)h * 65536 + (kb + 1) * 64;
            uint32_t dst = sb + OPB + ((kb + 1) & 1) * PBSTRIDE;
#pragma unroll 1
            for (int i = tid; i < 2048; i += 256) {
                int q = i >> 3, seg = i & 7;
                CP16(dst + q * 144 + seg * 16, pbB + (size_t)q * 256 + seg * 8);
            }
            CP_COMMIT();
            asm volatile("cp.async.wait_group 1;" ::: "memory");
        } else {
            asm volatile("cp.async.wait_group 0;" ::: "memory");
        }
        __syncthreads();

        float sfr[2][8][4] = {};
#pragma unroll
        for (int ks = 0; ks < 2; ks++)
#pragma unroll
            for (int ng = 0; ng < 4; ng++) {
                uint32_t kh[4], kl[4];
                uint32_t bd = sb + (kb * 64 + ng * 16 + bRow) * 80
                            + (ks * 16 + bChunk) * 2;
                LDM_A(kh, bd + OKH);
                LDM_A(kl, bd + OKL);
#pragma unroll
                for (int mi = 0; mi < 2; mi++) {
                    MMA_BF16(sfr[mi][ng * 2], ah[mi][ks], kh[0], kh[1]);
                    MMA_BF16(sfr[mi][ng * 2], ah[mi][ks], kl[0], kl[1]);
                    MMA_BF16(sfr[mi][ng * 2], al[mi][ks], kh[0], kh[1]);
                    MMA_BF16(sfr[mi][ng * 2 + 1], ah[mi][ks], kh[2], kh[3]);
                    MMA_BF16(sfr[mi][ng * 2 + 1], ah[mi][ks], kl[2], kl[3]);
                    MMA_BF16(sfr[mi][ng * 2 + 1], al[mi][ks], kh[2], kh[3]);
                }
            }

        uint32_t pbuf = sb + OPB + (kb & 1) * PBSTRIDE;
        const float* mbp = (const float*)(smb + OMB) + kb * 64;
#pragma unroll
        for (int mi = 0; mi < 2; mi++) {
            int q0 = w * 32 + mi * 16 + (lane >> 2);
#pragma unroll
            for (int nj = 0; nj < 8; nj++) {
                int cB = nj * 8 + (lane & 3) * 2;
                float2 mv = *(const float2*)(mbp + cB);
                uint32_t u0, u1;
                asm("ld.shared.b32 %0, [%1];" : "=r"(u0) : "r"(pbuf + q0 * 144 + cB * 2));
                asm("ld.shared.b32 %0, [%1];" : "=r"(u1) : "r"(pbuf + (q0 + 8) * 144 + cB * 2));
                float2 p0 = bfu2f2(u0), p1 = bfu2f2(u1);
                sfr[mi][nj][0] += mv.x + p0.x;
                sfr[mi][nj][1] += mv.y + p0.y;
                sfr[mi][nj][2] += mv.x + p1.x;
                sfr[mi][nj][3] += mv.y + p1.y;
            }
        }

#pragma unroll
        for (int mi = 0; mi < 2; mi++)
#pragma unroll
            for (int p = 0; p < 2; p++) {
                int id = mi * 2 + p;
                float mx = mrow[id];
#pragma unroll
                for (int nj = 0; nj < 8; nj++)
                    mx = fmaxf(mx, fmaxf(sfr[mi][nj][2 * p], sfr[mi][nj][2 * p + 1]));
                mx = fmaxf(mx, __shfl_xor_sync(0xffffffffu, mx, 1));
                mx = fmaxf(mx, __shfl_xor_sync(0xffffffffu, mx, 2));
                float es = ex2(mrow[id] - mx);
                mrow[id] = mx;
                float ls = 0.f;
#pragma unroll
                for (int nj = 0; nj < 8; nj++) {
                    float v0 = ex2(sfr[mi][nj][2 * p] - mx);
                    float v1 = ex2(sfr[mi][nj][2 * p + 1] - mx);
                    sfr[mi][nj][2 * p] = v0;
                    sfr[mi][nj][2 * p + 1] = v1;
                    ls += v0 + v1;
                }
                ls += __shfl_xor_sync(0xffffffffu, ls, 1);
                ls += __shfl_xor_sync(0xffffffffu, ls, 2);
                srow[id] = srow[id] * es + ls;
#pragma unroll
                for (int nc = 0; nc < 4; nc++) {
                    o[mi][nc][2 * p] *= es;
                    o[mi][nc][2 * p + 1] *= es;
                }
            }

#pragma unroll
        for (int t = 0; t < 4; t++) {
            uint32_t pa[2][4];
#pragma unroll
            for (int mi = 0; mi < 2; mi++) {
                pa[mi][0] = pk2(sfr[mi][2 * t][0], sfr[mi][2 * t][1]);
                pa[mi][1] = pk2(sfr[mi][2 * t][2], sfr[mi][2 * t][3]);
                pa[mi][2] = pk2(sfr[mi][2 * t + 1][0], sfr[mi][2 * t + 1][1]);
                pa[mi][3] = pk2(sfr[mi][2 * t + 1][2], sfr[mi][2 * t + 1][3]);
            }
#pragma unroll
            for (int ng = 0; ng < 2; ng++) {
                uint32_t vh[4], vl[4];
                uint32_t vd = (kb * 64 + t * 16 + vkRow) * 80 + (ng * 16 + vcCol) * 2;
                LDM_T(vh, sb + OVH + vd);
                LDM_T(vl, sb + OVL + vd);
#pragma unroll
                for (int mi = 0; mi < 2; mi++) {
                    MMA_BF16(o[mi][ng * 2], pa[mi], vh[0], vh[1]);
                    MMA_BF16(o[mi][ng * 2], pa[mi], vl[0], vl[1]);
                    MMA_BF16(o[mi][ng * 2 + 1], pa[mi], vh[2], vh[3]);
                    MMA_BF16(o[mi][ng * 2 + 1], pa[mi], vl[2], vl[3]);
                }
            }
        }
        __syncthreads();
    }

    // epilogue part 1: stage normalized O in smem (fp32, row stride 36 floats)
    float* stg = (float*)smb;
#pragma unroll
    for (int mi = 0; mi < 2; mi++)
#pragma unroll
        for (int p = 0; p < 2; p++) {
            float inv = 1.0f / srow[mi * 2 + p];
            int rr = w * 32 + mi * 16 + (lane >> 2) + p * 8;
#pragma unroll
            for (int nc = 0; nc < 4; nc++) {
                int cc = nc * 8 + (lane & 3) * 2;
                *(float2*)(stg + rr * 36 + cc) =
                    make_float2(o[mi][nc][2 * p] * inv, o[mi][nc][2 * p + 1] * inv);
            }
        }
    __syncthreads();

    // epilogue part 2: coalesced gated write-out (8 lanes cover one row)
    {
        int seg = tid & 7;            // 4 channels per thread
        int rbase = tid >> 3;         // 32 rows per pass
        int gc = h * 32 + seg * 4;
        float4 gb4 = *(const float4*)(gbias + gc);
#pragma unroll
        for (int pass = 0; pass < 8; pass++) {
            int rr = pass * 32 + rbase;
            size_t gr = (size_t)(s * 256 + rr) * 256 + gc;
            float4 ov = *(float4*)(stg + rr * 36 + seg * 4);
            float4 gl = *(const float4*)(g_gate + gr);
            float a0 = ov.x / (1.0f + __expf(-(gl.x + gb4.x)));
            float a1 = ov.y / (1.0f + __expf(-(gl.y + gb4.y)));
            float a2 = ov.z / (1.0f + __expf(-(gl.z + gb4.z)));
            float a3 = ov.w / (1.0f + __expf(-(gl.w + gb4.w)));
            __nv_bfloat162 h0, h1, l0, l1;
            h0.x = __float2bfloat16(a0); h0.y = __float2bfloat16(a1);
            h1.x = __float2bfloat16(a2); h1.y = __float2bfloat16(a3);
            l0.x = __float2bfloat16(a0 - __bfloat162float(h0.x));
            l0.y = __float2bfloat16(a1 - __bfloat162float(h0.y));
            l1.x = __float2bfloat16(a2 - __bfloat162float(h1.x));
            l1.y = __float2bfloat16(a3 - __bfloat162float(h1.y));
            uint2 hv, lv;
            hv.x = *(uint32_t*)&h0; hv.y = *(uint32_t*)&h1;
            lv.x = *(uint32_t*)&l0; lv.y = *(uint32_t*)&l1;
            *(uint2*)(g_Ah + gr) = hv;
            *(uint2*)(g_Al + gr) = lv;
        }
    }
}

// ---------------------------------------------------------------------------
// Kernel 5: out = A @ W_o^T + M_raw + out_bias (pure pipelined bf16 GEMM)
// ---------------------------------------------------------------------------
__global__ __launch_bounds__(256) void gemm_out_mma(
    const float* __restrict__ Mraw, const float* __restrict__ obias,
    float* __restrict__ out)
{
    extern __shared__ __align__(16) unsigned char smb[];
    uint32_t sbase = smem_u32(smb);
    int tid = threadIdx.x;
    int lane = tid & 31, wid = tid >> 5;
    int wm = wid >> 2, wn = wid & 3;
    int bm = blockIdx.y * 128, bn = blockIdx.x * 128;

    float acc[4][4][4] = {};

    int lrow = tid >> 1, lhalf = tid & 1;
    size_t gA = (size_t)(bm + lrow) * 256 + lhalf * 16;
    size_t gB = (size_t)(bn + lrow) * 256 + lhalf * 16;
    uint32_t sOff = lrow * 80 + lhalf * 32;

    uint32_t aRow = (lane & 15);
    uint32_t aChunk = (lane >> 4) << 3;
    uint32_t bRow = (lane & 7) + ((lane >> 4) << 3);
    uint32_t bChunk = ((lane >> 3) & 1) << 3;

    {
        uint32_t b = sbase;
        CP16(b + OFF_AH + sOff, g_Ah + gA); CP16(b + OFF_AH + sOff + 16, g_Ah + gA + 8);
        CP16(b + OFF_AL + sOff, g_Al + gA); CP16(b + OFF_AL + sOff + 16, g_Al + gA + 8);
        CP16(b + OFF_BH + sOff, g_Oh + gB); CP16(b + OFF_BH + sOff + 16, g_Oh + gB + 8);
        CP16(b + OFF_BL + sOff, g_Ol + gB); CP16(b + OFF_BL + sOff + 16, g_Ol + gB + 8);
        CP_COMMIT();
    }

#pragma unroll 1
    for (int t = 0; t < 8; t++) {
        if (t < 7) {
            int c = t + 1;
            uint32_t b = sbase + (c & 1) * PROJ_STAGE;
            const __nv_bfloat16* p;
            p = g_Ah + gA + c * 32;
            CP16(b + OFF_AH + sOff, p); CP16(b + OFF_AH + sOff + 16, p + 8);
            p = g_Al + gA + c * 32;
            CP16(b + OFF_AL + sOff, p); CP16(b + OFF_AL + sOff + 16, p + 8);
            p = g_Oh + gB + c * 32;
            CP16(b + OFF_BH + sOff, p); CP16(b + OFF_BH + sOff + 16, p + 8);
            p = g_Ol + gB + c * 32;
            CP16(b + OFF_BL + sOff, p); CP16(b + OFF_BL + sOff + 16, p + 8);
            CP_COMMIT();
            asm volatile("cp.async.wait_group 1;" ::: "memory");
        } else {
            asm volatile("cp.async.wait_group 0;" ::: "memory");
        }
        __syncthreads();

        uint32_t sb = sbase + (t & 1) * PROJ_STAGE;
#pragma unroll
        for (int ks = 0; ks < 2; ks++) {
            uint32_t ah[4][4], al[4][4], bh[2][4], bl[2][4];
#pragma unroll
            for (int mi = 0; mi < 4; mi++) {
                uint32_t ad = sb + (wm * 64 + mi * 16 + aRow) * 80
                            + (ks * 16 + aChunk) * 2;
                LDM_A(ah[mi], ad + OFF_AH);
                LDM_A(al[mi], ad + OFF_AL);
            }
#pragma unroll
            for (int ng = 0; ng < 2; ng++) {
                uint32_t bd = sb + (wn * 32 + ng * 16 + bRow) * 80
                            + (ks * 16 + bChunk) * 2;
                LDM_A(bh[ng], bd + OFF_BH);
                LDM_A(bl[ng], bd + OFF_BL);
            }
#pragma unroll
            for (int mi = 0; mi < 4; mi++) {
#pragma unroll
                for (int nj = 0; nj < 4; nj++) {
                    int ng = nj >> 1, sub = (nj & 1) * 2;
                    MMA_BF16(acc[mi][nj], ah[mi], bh[ng][sub], bh[ng][sub + 1]);
                    MMA_BF16(acc[mi][nj], ah[mi], bl[ng][sub], bl[ng][sub + 1]);
                    MMA_BF16(acc[mi][nj], al[mi], bh[ng][sub], bh[ng][sub + 1]);
                }
            }
        }
        __syncthreads();
    }

    int r0 = bm + wm * 64 + (lane >> 2);
    int c0 = bn + wn * 32 + (lane & 3) * 2;
#pragma unroll
    for (int mi = 0; mi < 4; mi++) {
#pragma unroll
        for (int nj = 0; nj < 4; nj++) {
            int r = r0 + mi * 16, c = c0 + nj * 8;
            float ob0 = obias[c], ob1 = obias[c + 1];
            float2 m0 = *(const float2*)(Mraw + (size_t)r * 256 + c);
            *(float2*)(out + (size_t)r * 256 + c) =
                make_float2(acc[mi][nj][0] + m0.x + ob0, acc[mi][nj][1] + m0.y + ob1);
            float2 m1 = *(const float2*)(Mraw + (size_t)(r + 8) * 256 + c);
            *(float2*)(out + (size_t)(r + 8) * 256 + c) =
                make_float2(acc[mi][nj][2] + m1.x + ob0, acc[mi][nj][3] + m1.y + ob1);
        }
    }
}

// ---------------------------------------------------------------------------
extern "C" void kernel_launch(void* const* d_in, const int* in_sizes, int n_in,
                              void* d_out, int out_size)
{
    const float* M_raw      = (const float*)d_in[0];
    const float* Z          = (const float*)d_in[1];
    const float* M_mask     = (const float*)d_in[2];
    const float* ln_m_scale = (const float*)d_in[3];
    const float* ln_m_bias  = (const float*)d_in[4];
    const float* ln_z_scale = (const float*)d_in[5];
    const float* ln_z_bias  = (const float*)d_in[6];
    const float* W_b        = (const float*)d_in[7];
    const float* W_qkv      = (const float*)d_in[8];
    const float* W_gate     = (const float*)d_in[9];
    const float* gbias      = (const float*)d_in[10];
    const float* W_o        = (const float*)d_in[11];
    const float* out_bias   = (const float*)d_in[12];
    float* out = (float*)d_out;

    cudaFuncSetAttribute(gemm_proj_mma, cudaFuncAttributeMaxDynamicSharedMemorySize,
                         PROJ_SMEM);
    cudaFuncSetAttribute(attn_mma, cudaFuncAttributeMaxDynamicSharedMemorySize,
                         ATTN_SMEM);
    cudaFuncSetAttribute(gemm_out_mma, cudaFuncAttributeMaxDynamicSharedMemorySize,
                         PROJ_SMEM);

    prep_kernel<<<PREP_TOT, 256>>>(M_raw, ln_m_scale, ln_m_bias,
                                   W_qkv, W_gate, W_o,
                                   Z, ln_z_scale, ln_z_bias, W_b);
    gemm_proj_mma<<<dim3(EPROJ / 128, NROWS / 128), 256, PROJ_SMEM>>>();
    attn_mma<<<dim3(NHEAD, NSEQ), 256, ATTN_SMEM>>>(M_mask, gbias);
    gemm_out_mma<<<dim3(256 / 128, NROWS / 128), 256, PROJ_SMEM>>>(M_raw, out_bias, out);
}

// round 10
// speedup vs baseline: 1.6639x; 1.6567x over previous
#include <cuda_runtime.h>
#include <cuda_fp16.h>
#include <cstdint>
#include <math.h>

// Problem constants
#define D_NODE 256
#define D_PAIR 128
#define NHEAD  8
#define NSEQ   128
#define NRES   256
#define NROWS  (NSEQ * NRES)          // 32768
#define EPROJ  1024                    // 768 qkv + 256 gate

#define LOG2E 1.4426950408889634f

// Scratch (all fp16 single-precision operands)
__device__ __half g_M[(size_t)NROWS * D_NODE];       // LN(M)
__device__ __half g_W[(size_t)EPROJ * D_NODE];       // [Wqkv;Wgate]
__device__ __half g_O[(size_t)D_NODE * D_NODE];      // W_o
__device__ __half g_X[(size_t)NROWS * 768];          // q(scaled)|k|v
__device__ __half g_gate[(size_t)NROWS * 256];       // gate logits
__device__ __half g_pb[(size_t)NHEAD * NRES * NRES]; // pair bias*log2e [h][q][k]
__device__ __half g_A[(size_t)NROWS * D_NODE];       // gated attn out

__device__ __forceinline__ uint32_t smem_u32(const void* p) {
    uint32_t a;
    asm("{ .reg .u64 t; cvta.to.shared.u64 t, %1; cvt.u32.u64 %0, t; }"
        : "=r"(a) : "l"(p));
    return a;
}

#define LDM_X4(r0, r1, r2, r3, addr)                                           \
    asm volatile("ldmatrix.sync.aligned.m8n8.x4.shared.b16 {%0,%1,%2,%3}, [%4];" \
                 : "=r"(r0), "=r"(r1), "=r"(r2), "=r"(r3) : "r"(addr))
#define LDM_A(v, addr) LDM_X4((v)[0], (v)[1], (v)[2], (v)[3], addr)

#define LDM_T(v, addr)                                                         \
    asm volatile("ldmatrix.sync.aligned.m8n8.x4.trans.shared.b16 {%0,%1,%2,%3}, [%4];" \
                 : "=r"((v)[0]), "=r"((v)[1]), "=r"((v)[2]), "=r"((v)[3]) : "r"(addr))

#define MMA_F16(d, a, b0, b1)                                                  \
    asm volatile("mma.sync.aligned.m16n8k16.row.col.f32.f16.f16.f32 "          \
                 "{%0,%1,%2,%3}, {%4,%5,%6,%7}, {%8,%9}, {%0,%1,%2,%3};"       \
                 : "+f"((d)[0]), "+f"((d)[1]), "+f"((d)[2]), "+f"((d)[3])      \
                 : "r"((a)[0]), "r"((a)[1]), "r"((a)[2]), "r"((a)[3]),         \
                   "r"(b0), "r"(b1))

#define CP16(s, g)                                                             \
    asm volatile("cp.async.cg.shared.global [%0], [%1], 16;" :: "r"(s), "l"(g))
#define CP_COMMIT() asm volatile("cp.async.commit_group;" ::: "memory")

__device__ __forceinline__ uint32_t pk2(float lo, float hi) {
    __half2 h = __floats2half2_rn(lo, hi);      // .x = lo (low half)
    return *reinterpret_cast<uint32_t*>(&h);
}
__device__ __forceinline__ float2 h2f2(uint32_t u) {
    __half2 h = *reinterpret_cast<__half2*>(&u);
    return __half22float2(h);
}
__device__ __forceinline__ float ex2(float x) {
    float r;
    asm("ex2.approx.f32 %0, %1;" : "=f"(r) : "f"(x));
    return r;
}

__device__ __forceinline__ float warp_sum(float v) {
#pragma unroll
    for (int o = 16; o > 0; o >>= 1) v += __shfl_xor_sync(0xffffffffu, v, o);
    return v;
}

// ---------------------------------------------------------------------------
// Kernel 1 (fused preprocessing): ln_m | wconv | wconv_o | pair  -> fp16
// ---------------------------------------------------------------------------
#define PREP_LN  4096
#define PREP_WC  (PREP_LN + 1024)   // 5120
#define PREP_WO  (PREP_WC + 256)    // 5376
#define PREP_TOT (PREP_WO + 8192)   // 13568

__global__ __launch_bounds__(256) void prep_kernel(
    const float* __restrict__ M_raw, const float* __restrict__ mlsc,
    const float* __restrict__ mlbi,
    const float* __restrict__ Wq, const float* __restrict__ Wg,
    const float* __restrict__ Wo,
    const float* __restrict__ Z, const float* __restrict__ zsc,
    const float* __restrict__ zbi, const float* __restrict__ Wb)
{
    __shared__ float swb[1024];
    __shared__ float ssc[128], sbi[128];
    __shared__ float spb[64];

    int b = blockIdx.x;
    int tid = threadIdx.x;

    if (b < PREP_LN) {
        int w = tid >> 5, l = tid & 31;
        int row = b * 8 + w;
        const float4* xr = (const float4*)(M_raw + (size_t)row * 256);
        float4 a = xr[l], bb = xr[l + 32];
        float s1 = (a.x + a.y) + (a.z + a.w) + (bb.x + bb.y) + (bb.z + bb.w);
        float s2 = a.x * a.x + a.y * a.y + a.z * a.z + a.w * a.w
                 + bb.x * bb.x + bb.y * bb.y + bb.z * bb.z + bb.w * bb.w;
        s1 = warp_sum(s1);
        s2 = warp_sum(s2);
        float mu  = s1 * (1.0f / 256.0f);
        float var = s2 * (1.0f / 256.0f) - mu * mu;
        float inv = rsqrtf(var + 1e-5f);

        float4 sa = ((const float4*)mlsc)[l], sb4 = ((const float4*)mlsc)[l + 32];
        float4 ba = ((const float4*)mlbi)[l], bb4 = ((const float4*)mlbi)[l + 32];

        __half* mh = g_M + (size_t)row * 256;
        {
            int c = l * 4;
            *(__half2*)(mh + c) = __floats2half2_rn(
                (a.x - mu) * inv * sa.x + ba.x, (a.y - mu) * inv * sa.y + ba.y);
            *(__half2*)(mh + c + 2) = __floats2half2_rn(
                (a.z - mu) * inv * sa.z + ba.z, (a.w - mu) * inv * sa.w + ba.w);
            c += 128;
            *(__half2*)(mh + c) = __floats2half2_rn(
                (bb.x - mu) * inv * sb4.x + bb4.x, (bb.y - mu) * inv * sb4.y + bb4.y);
            *(__half2*)(mh + c + 2) = __floats2half2_rn(
                (bb.z - mu) * inv * sb4.z + bb4.z, (bb.w - mu) * inv * sb4.w + bb4.w);
        }
    } else if (b < PREP_WC) {
        int i = (b - PREP_LN) * 256 + tid;
        float v = (i < 768 * 256) ? Wq[i] : Wg[i - 768 * 256];
        g_W[i] = __float2half_rn(v);
    } else if (b < PREP_WO) {
        int i = (b - PREP_WC) * 256 + tid;
        g_O[i] = __float2half_rn(Wo[i]);
    } else {
        int pb = b - PREP_WO;
        if (tid < 128) { ssc[tid] = zsc[tid]; sbi[tid] = zbi[tid]; }
        ((float4*)swb)[tid] = ((const float4*)Wb)[tid];
        __syncthreads();

        int w = tid >> 5, l = tid & 31;
        int row = pb * 8 + w;                // = q*256 + k
        float4 z = ((const float4*)(Z + (size_t)row * 128))[l];
        float s1 = (z.x + z.y) + (z.z + z.w);
        float s2 = z.x * z.x + z.y * z.y + z.z * z.z + z.w * z.w;
        s1 = warp_sum(s1);
        s2 = warp_sum(s2);
        float mu  = s1 * (1.0f / 128.0f);
        float var = s2 * (1.0f / 128.0f) - mu * mu;
        float inv = rsqrtf(var + 1e-5f);
        int c = l * 4;
        float zn0 = (z.x - mu) * inv * ssc[c]     + sbi[c];
        float zn1 = (z.y - mu) * inv * ssc[c + 1] + sbi[c + 1];
        float zn2 = (z.z - mu) * inv * ssc[c + 2] + sbi[c + 2];
        float zn3 = (z.w - mu) * inv * ssc[c + 3] + sbi[c + 3];

        float p[8];
#pragma unroll
        for (int hh = 0; hh < 8; hh++) {
            float4 wb4 = ((const float4*)swb)[hh * 32 + l];
            p[hh] = zn0 * wb4.x + zn1 * wb4.y + zn2 * wb4.z + zn3 * wb4.w;
        }
#pragma unroll
        for (int hh = 0; hh < 8; hh++) p[hh] += __shfl_xor_sync(0xffffffffu, p[hh], 16);
        float q0 = (l & 16) ? p[4] : p[0];
        float q1 = (l & 16) ? p[5] : p[1];
        float q2 = (l & 16) ? p[6] : p[2];
        float q3 = (l & 16) ? p[7] : p[3];
        q0 += __shfl_xor_sync(0xffffffffu, q0, 8);
        q1 += __shfl_xor_sync(0xffffffffu, q1, 8);
        q2 += __shfl_xor_sync(0xffffffffu, q2, 8);
        q3 += __shfl_xor_sync(0xffffffffu, q3, 8);
        float r0 = (l & 8) ? q2 : q0;
        float r1 = (l & 8) ? q3 : q1;
        r0 += __shfl_xor_sync(0xffffffffu, r0, 4);
        r1 += __shfl_xor_sync(0xffffffffu, r1, 4);
        float s0 = (l & 4) ? r1 : r0;
        s0 += __shfl_xor_sync(0xffffffffu, s0, 2);
        s0 += __shfl_xor_sync(0xffffffffu, s0, 1);
        if ((l & 3) == 0) spb[w * 8 + (l >> 2)] = s0 * LOG2E;
        __syncthreads();
        if (tid < 64) {
            int hh = tid >> 3, j = tid & 7;
            int row0 = pb * 8;
            int qq = row0 >> 8, k0 = row0 & 255;
            g_pb[(size_t)hh * 65536 + qq * 256 + k0 + j] = __float2half_rn(spb[j * 8 + hh]);
        }
    }
}

// ---------------------------------------------------------------------------
// Kernel 3: projection GEMM (mma.sync fp16 single-term, cp.async 2-stage).
// BM=128 BN=128 BK=32; writes q(scaled by log2e/sqrt32)|k|v and gate fp16.
// ---------------------------------------------------------------------------
#define PSTG_A 0
#define PSTG_B 10240
#define PSTAGE 20480
#define PSMEM  (2 * PSTAGE)

__global__ __launch_bounds__(256) void gemm_proj_mma()
{
    extern __shared__ __align__(16) unsigned char smb[];
    uint32_t sbase = smem_u32(smb);
    int tid = threadIdx.x;
    int lane = tid & 31, wid = tid >> 5;
    int wm = wid >> 2, wn = wid & 3;
    int bm = blockIdx.y * 128, bn = blockIdx.x * 128;

    float acc[4][4][4] = {};

    int lrow = tid >> 1, lhalf = tid & 1;
    size_t gA = (size_t)(bm + lrow) * 256 + lhalf * 16;
    size_t gB = (size_t)(bn + lrow) * 256 + lhalf * 16;
    uint32_t sOff = lrow * 80 + lhalf * 32;

    uint32_t aRow = (lane & 15);
    uint32_t aChunk = (lane >> 4) << 3;
    uint32_t bRow = (lane & 7) + ((lane >> 4) << 3);
    uint32_t bChunk = ((lane >> 3) & 1) << 3;

    {
        uint32_t b = sbase;
        CP16(b + PSTG_A + sOff, g_M + gA); CP16(b + PSTG_A + sOff + 16, g_M + gA + 8);
        CP16(b + PSTG_B + sOff, g_W + gB); CP16(b + PSTG_B + sOff + 16, g_W + gB + 8);
        CP_COMMIT();
    }

#pragma unroll 1
    for (int t = 0; t < 8; t++) {
        if (t < 7) {
            int c = t + 1;
            uint32_t b = sbase + (c & 1) * PSTAGE;
            const __half* p;
            p = g_M + gA + c * 32;
            CP16(b + PSTG_A + sOff, p); CP16(b + PSTG_A + sOff + 16, p + 8);
            p = g_W + gB + c * 32;
            CP16(b + PSTG_B + sOff, p); CP16(b + PSTG_B + sOff + 16, p + 8);
            CP_COMMIT();
            asm volatile("cp.async.wait_group 1;" ::: "memory");
        } else {
            asm volatile("cp.async.wait_group 0;" ::: "memory");
        }
        __syncthreads();

        uint32_t sb = sbase + (t & 1) * PSTAGE;
#pragma unroll
        for (int ks = 0; ks < 2; ks++) {
            uint32_t ah[4][4], bh[2][4];
#pragma unroll
            for (int mi = 0; mi < 4; mi++) {
                uint32_t ad = sb + PSTG_A + (wm * 64 + mi * 16 + aRow) * 80
                            + (ks * 16 + aChunk) * 2;
                LDM_A(ah[mi], ad);
            }
#pragma unroll
            for (int ng = 0; ng < 2; ng++) {
                uint32_t bd = sb + PSTG_B + (wn * 32 + ng * 16 + bRow) * 80
                            + (ks * 16 + bChunk) * 2;
                LDM_A(bh[ng], bd);
            }
#pragma unroll
            for (int mi = 0; mi < 4; mi++) {
#pragma unroll
                for (int nj = 0; nj < 4; nj++) {
                    int ng = nj >> 1, sub = (nj & 1) * 2;
                    MMA_F16(acc[mi][nj], ah[mi], bh[ng][sub], bh[ng][sub + 1]);
                }
            }
        }
        __syncthreads();
    }

    int r0 = bm + wm * 64 + (lane >> 2);
    int c0 = bn + wn * 32 + (lane & 3) * 2;
    if (bn < 768) {
        float sc = (bn < 256) ? (0.17677669529663688f * LOG2E) : 1.0f;
#pragma unroll
        for (int mi = 0; mi < 4; mi++) {
#pragma unroll
            for (int nj = 0; nj < 4; nj++) {
                int c = c0 + nj * 8;
#pragma unroll
                for (int p = 0; p < 2; p++) {
                    int r = r0 + mi * 16 + p * 8;
                    *(__half2*)(g_X + (size_t)r * 768 + c) =
                        __floats2half2_rn(acc[mi][nj][2 * p] * sc,
                                          acc[mi][nj][2 * p + 1] * sc);
                }
            }
        }
    } else {
#pragma unroll
        for (int mi = 0; mi < 4; mi++) {
#pragma unroll
            for (int nj = 0; nj < 4; nj++) {
                int c = c0 + nj * 8 - 768;
#pragma unroll
                for (int p = 0; p < 2; p++) {
                    int r = r0 + mi * 16 + p * 8;
                    *(__half2*)(g_gate + (size_t)r * 256 + c) =
                        __floats2half2_rn(acc[mi][nj][2 * p], acc[mi][nj][2 * p + 1]);
                }
            }
        }
    }
}

// ---------------------------------------------------------------------------
// Kernel 4: flash attention via mma.sync fp16 single-term (exp2 softmax);
// epilogue stages O in smem then coalesced gated write-out of fp16 A.
// ---------------------------------------------------------------------------
#define OQ  0
#define OK  20480
#define OV  40960
#define OPB 61440
#define PBSTRIDE 36864
#define OMB (OPB + 2 * PBSTRIDE)      // 135168
#define ATTN_SMEM (OMB + 1024)        // 136192

__global__ __launch_bounds__(256) void attn_mma(
    const float* __restrict__ mask, const float* __restrict__ gbias)
{
    extern __shared__ __align__(16) unsigned char smb[];
    uint32_t sb = smem_u32(smb);
    int tid = threadIdx.x;
    int lane = tid & 31, w = tid >> 5;
    int h = blockIdx.x, s = blockIdx.y;

    const __half* XB = g_X + (size_t)s * 256 * 768;

#pragma unroll 1
    for (int i = tid; i < 1024; i += 256) {
        int r = i >> 2, seg = i & 3;
        uint32_t d = r * 80 + seg * 16;
        size_t off = (size_t)r * 768 + h * 32 + seg * 8;
        CP16(sb + OQ + d, XB + off);
        CP16(sb + OK + d, XB + off + 256);
        CP16(sb + OV + d, XB + off + 512);
    }
    {
        const __half* pbB = g_pb + (size_t)h * 65536;
#pragma unroll 1
        for (int i = tid; i < 2048; i += 256) {
            int q = i >> 3, seg = i & 7;
            CP16(sb + OPB + q * 144 + seg * 16, pbB + (size_t)q * 256 + seg * 8);
        }
    }
    CP_COMMIT();
    ((float*)(smb + OMB))[tid] = (1e9f * LOG2E) * (mask[s * 256 + tid] - 1.0f);
    asm volatile("cp.async.wait_group 0;" ::: "memory");
    __syncthreads();

    uint32_t aRow = lane & 15, aChunk = (lane >> 4) << 3;
    uint32_t bRow = (lane & 7) + ((lane >> 4) << 3);
    uint32_t bChunk = ((lane >> 3) & 1) << 3;
    uint32_t vkRow = (lane & 7) + (((lane >> 3) & 1) << 3);
    uint32_t vcCol = (lane >> 4) << 3;

    uint32_t ah[2][2][4];
#pragma unroll
    for (int mi = 0; mi < 2; mi++)
#pragma unroll
        for (int ks = 0; ks < 2; ks++) {
            uint32_t ad = sb + OQ + (w * 32 + mi * 16 + aRow) * 80
                        + (ks * 16 + aChunk) * 2;
            LDM_A(ah[mi][ks], ad);
        }

    float o[2][4][4] = {};
    float mrow[4] = {-1e30f, -1e30f, -1e30f, -1e30f};
    float srow[4] = {};

#pragma unroll 1
    for (int kb = 0; kb < 4; kb++) {
        if (kb < 3) {
            const __half* pbB = g_pb + (size_t)h * 65536 + (kb + 1) * 64;
            uint32_t dst = sb + OPB + ((kb + 1) & 1) * PBSTRIDE;
#pragma unroll 1
            for (int i = tid; i < 2048; i += 256) {
                int q = i >> 3, seg = i & 7;
                CP16(dst + q * 144 + seg * 16, pbB + (size_t)q * 256 + seg * 8);
            }
            CP_COMMIT();
            asm volatile("cp.async.wait_group 1;" ::: "memory");
        } else {
            asm volatile("cp.async.wait_group 0;" ::: "memory");
        }
        __syncthreads();

        float sfr[2][8][4] = {};
        // S = Q K^T (single fp16 term)
#pragma unroll
        for (int ks = 0; ks < 2; ks++)
#pragma unroll
            for (int ng = 0; ng < 4; ng++) {
                uint32_t kh[4];
                uint32_t bd = sb + OK + (kb * 64 + ng * 16 + bRow) * 80
                            + (ks * 16 + bChunk) * 2;
                LDM_A(kh, bd);
#pragma unroll
                for (int mi = 0; mi < 2; mi++) {
                    MMA_F16(sfr[mi][ng * 2], ah[mi][ks], kh[0], kh[1]);
                    MMA_F16(sfr[mi][ng * 2 + 1], ah[mi][ks], kh[2], kh[3]);
                }
            }

        // add mask bias + pair bias
        uint32_t pbuf = sb + OPB + (kb & 1) * PBSTRIDE;
        const float* mbp = (const float*)(smb + OMB) + kb * 64;
#pragma unroll
        for (int mi = 0; mi < 2; mi++) {
            int q0 = w * 32 + mi * 16 + (lane >> 2);
#pragma unroll
            for (int nj = 0; nj < 8; nj++) {
                int cB = nj * 8 + (lane & 3) * 2;
                float2 mv = *(const float2*)(mbp + cB);
                uint32_t u0, u1;
                asm("ld.shared.b32 %0, [%1];" : "=r"(u0) : "r"(pbuf + q0 * 144 + cB * 2));
                asm("ld.shared.b32 %0, [%1];" : "=r"(u1) : "r"(pbuf + (q0 + 8) * 144 + cB * 2));
                float2 p0 = h2f2(u0), p1 = h2f2(u1);
                sfr[mi][nj][0] += mv.x + p0.x;
                sfr[mi][nj][1] += mv.y + p0.y;
                sfr[mi][nj][2] += mv.x + p1.x;
                sfr[mi][nj][3] += mv.y + p1.y;
            }
        }

        // online softmax (exp2 domain, quad reduction)
#pragma unroll
        for (int mi = 0; mi < 2; mi++)
#pragma unroll
            for (int p = 0; p < 2; p++) {
                int id = mi * 2 + p;
                float mx = mrow[id];
#pragma unroll
                for (int nj = 0; nj < 8; nj++)
                    mx = fmaxf(mx, fmaxf(sfr[mi][nj][2 * p], sfr[mi][nj][2 * p + 1]));
                mx = fmaxf(mx, __shfl_xor_sync(0xffffffffu, mx, 1));
                mx = fmaxf(mx, __shfl_xor_sync(0xffffffffu, mx, 2));
                float es = ex2(mrow[id] - mx);
                mrow[id] = mx;
                float ls = 0.f;
#pragma unroll
                for (int nj = 0; nj < 8; nj++) {
                    float v0 = ex2(sfr[mi][nj][2 * p] - mx);
                    float v1 = ex2(sfr[mi][nj][2 * p + 1] - mx);
                    sfr[mi][nj][2 * p] = v0;
                    sfr[mi][nj][2 * p + 1] = v1;
                    ls += v0 + v1;
                }
                ls += __shfl_xor_sync(0xffffffffu, ls, 1);
                ls += __shfl_xor_sync(0xffffffffu, ls, 2);
                srow[id] = srow[id] * es + ls;
#pragma unroll
                for (int nc = 0; nc < 4; nc++) {
                    o[mi][nc][2 * p] *= es;
                    o[mi][nc][2 * p + 1] *= es;
                }
            }

        // O += P V (single fp16 term, trans-loaded V)
#pragma unroll
        for (int t = 0; t < 4; t++) {
            uint32_t pa[2][4];
#pragma unroll
            for (int mi = 0; mi < 2; mi++) {
                pa[mi][0] = pk2(sfr[mi][2 * t][0], sfr[mi][2 * t][1]);
                pa[mi][1] = pk2(sfr[mi][2 * t][2], sfr[mi][2 * t][3]);
                pa[mi][2] = pk2(sfr[mi][2 * t + 1][0], sfr[mi][2 * t + 1][1]);
                pa[mi][3] = pk2(sfr[mi][2 * t + 1][2], sfr[mi][2 * t + 1][3]);
            }
#pragma unroll
            for (int ng = 0; ng < 2; ng++) {
                uint32_t vh[4];
                uint32_t vd = sb + OV + (kb * 64 + t * 16 + vkRow) * 80
                            + (ng * 16 + vcCol) * 2;
                LDM_T(vh, vd);
#pragma unroll
                for (int mi = 0; mi < 2; mi++) {
                    MMA_F16(o[mi][ng * 2], pa[mi], vh[0], vh[1]);
                    MMA_F16(o[mi][ng * 2 + 1], pa[mi], vh[2], vh[3]);
                }
            }
        }
        __syncthreads();
    }

    // epilogue part 1: stage normalized O in smem (fp32, row stride 36 floats)
    float* stg = (float*)smb;
#pragma unroll
    for (int mi = 0; mi < 2; mi++)
#pragma unroll
        for (int p = 0; p < 2; p++) {
            float inv = 1.0f / srow[mi * 2 + p];
            int rr = w * 32 + mi * 16 + (lane >> 2) + p * 8;
#pragma unroll
            for (int nc = 0; nc < 4; nc++) {
                int cc = nc * 8 + (lane & 3) * 2;
                *(float2*)(stg + rr * 36 + cc) =
                    make_float2(o[mi][nc][2 * p] * inv, o[mi][nc][2 * p + 1] * inv);
            }
        }
    __syncthreads();

    // epilogue part 2: coalesced gated write-out (8 lanes cover one row)
    {
        int seg = tid & 7;            // 4 channels per thread
        int rbase = tid >> 3;         // 32 rows per pass
        int gc = h * 32 + seg * 4;
        float4 gb4 = *(const float4*)(gbias + gc);
#pragma unroll
        for (int pass = 0; pass < 8; pass++) {
            int rr = pass * 32 + rbase;
            size_t gr = (size_t)(s * 256 + rr) * 256 + gc;
            float4 ov = *(float4*)(stg + rr * 36 + seg * 4);
            uint2 gu = *(const uint2*)(g_gate + gr);
            float2 gl0 = h2f2(gu.x), gl1 = h2f2(gu.y);
            float a0 = ov.x / (1.0f + __expf(-(gl0.x + gb4.x)));
            float a1 = ov.y / (1.0f + __expf(-(gl0.y + gb4.y)));
            float a2 = ov.z / (1.0f + __expf(-(gl1.x + gb4.z)));
            float a3 = ov.w / (1.0f + __expf(-(gl1.y + gb4.w)));
            uint2 hv;
            hv.x = pk2(a0, a1);
            hv.y = pk2(a2, a3);
            *(uint2*)(g_A + gr) = hv;
        }
    }
}

// ---------------------------------------------------------------------------
// Kernel 5: out = A @ W_o^T + M_raw + out_bias (pipelined fp16 single-term)
// ---------------------------------------------------------------------------
__global__ __launch_bounds__(256) void gemm_out_mma(
    const float* __restrict__ Mraw, const float* __restrict__ obias,
    float* __restrict__ out)
{
    extern __shared__ __align__(16) unsigned char smb[];
    uint32_t sbase = smem_u32(smb);
    int tid = threadIdx.x;
    int lane = tid & 31, wid = tid >> 5;
    int wm = wid >> 2, wn = wid & 3;
    int bm = blockIdx.y * 128, bn = blockIdx.x * 128;

    float acc[4][4][4] = {};

    int lrow = tid >> 1, lhalf = tid & 1;
    size_t gA = (size_t)(bm + lrow) * 256 + lhalf * 16;
    size_t gB = (size_t)(bn + lrow) * 256 + lhalf * 16;
    uint32_t sOff = lrow * 80 + lhalf * 32;

    uint32_t aRow = (lane & 15);
    uint32_t aChunk = (lane >> 4) << 3;
    uint32_t bRow = (lane & 7) + ((lane >> 4) << 3);
    uint32_t bChunk = ((lane >> 3) & 1) << 3;

    {
        uint32_t b = sbase;
        CP16(b + PSTG_A + sOff, g_A + gA); CP16(b + PSTG_A + sOff + 16, g_A + gA + 8);
        CP16(b + PSTG_B + sOff, g_O + gB); CP16(b + PSTG_B + sOff + 16, g_O + gB + 8);
        CP_COMMIT();
    }

#pragma unroll 1
    for (int t = 0; t < 8; t++) {
        if (t < 7) {
            int c = t + 1;
            uint32_t b = sbase + (c & 1) * PSTAGE;
            const __half* p;
            p = g_A + gA + c * 32;
            CP16(b + PSTG_A + sOff, p); CP16(b + PSTG_A + sOff + 16, p + 8);
            p = g_O + gB + c * 32;
            CP16(b + PSTG_B + sOff, p); CP16(b + PSTG_B + sOff + 16, p + 8);
            CP_COMMIT();
            asm volatile("cp.async.wait_group 1;" ::: "memory");
        } else {
            asm volatile("cp.async.wait_group 0;" ::: "memory");
        }
        __syncthreads();

        uint32_t sb = sbase + (t & 1) * PSTAGE;
#pragma unroll
        for (int ks = 0; ks < 2; ks++) {
            uint32_t ah[4][4], bh[2][4];
#pragma unroll
            for (int mi = 0; mi < 4; mi++) {
                uint32_t ad = sb + PSTG_A + (wm * 64 + mi * 16 + aRow) * 80
                            + (ks * 16 + aChunk) * 2;
                LDM_A(ah[mi], ad);
            }
#pragma unroll
            for (int ng = 0; ng < 2; ng++) {
                uint32_t bd = sb + PSTG_B + (wn * 32 + ng * 16 + bRow) * 80
                            + (ks * 16 + bChunk) * 2;
                LDM_A(bh[ng], bd);
            }
#pragma unroll
            for (int mi = 0; mi < 4; mi++) {
#pragma unroll
                for (int nj = 0; nj < 4; nj++) {
                    int ng = nj >> 1, sub = (nj & 1) * 2;
                    MMA_F16(acc[mi][nj], ah[mi], bh[ng][sub], bh[ng][sub + 1]);
                }
            }
        }
        __syncthreads();
    }

    int r0 = bm + wm * 64 + (lane >> 2);
    int c0 = bn + wn * 32 + (lane & 3) * 2;
#pragma unroll
    for (int mi = 0; mi < 4; mi++) {
#pragma unroll
        for (int nj = 0; nj < 4; nj++) {
            int r = r0 + mi * 16, c = c0 + nj * 8;
            float ob0 = obias[c], ob1 = obias[c + 1];
            float2 m0 = *(const float2*)(Mraw + (size_t)r * 256 + c);
            *(float2*)(out + (size_t)r * 256 + c) =
                make_float2(acc[mi][nj][0] + m0.x + ob0, acc[mi][nj][1] + m0.y + ob1);
            float2 m1 = *(const float2*)(Mraw + (size_t)(r + 8) * 256 + c);
            *(float2*)(out + (size_t)(r + 8) * 256 + c) =
                make_float2(acc[mi][nj][2] + m1.x + ob0, acc[mi][nj][3] + m1.y + ob1);
        }
    }
}

// ---------------------------------------------------------------------------
extern "C" void kernel_launch(void* const* d_in, const int* in_sizes, int n_in,
                              void* d_out, int out_size)
{
    const float* M_raw      = (const float*)d_in[0];
    const float* Z          = (const float*)d_in[1];
    const float* M_mask     = (const float*)d_in[2];
    const float* ln_m_scale = (const float*)d_in[3];
    const float* ln_m_bias  = (const float*)d_in[4];
    const float* ln_z_scale = (const float*)d_in[5];
    const float* ln_z_bias  = (const float*)d_in[6];
    const float* W_b        = (const float*)d_in[7];
    const float* W_qkv      = (const float*)d_in[8];
    const float* W_gate     = (const float*)d_in[9];
    const float* gbias      = (const float*)d_in[10];
    const float* W_o        = (const float*)d_in[11];
    const float* out_bias   = (const float*)d_in[12];
    float* out = (float*)d_out;

    cudaFuncSetAttribute(attn_mma, cudaFuncAttributeMaxDynamicSharedMemorySize,
                         ATTN_SMEM);

    prep_kernel<<<PREP_TOT, 256>>>(M_raw, ln_m_scale, ln_m_bias,
                                   W_qkv, W_gate, W_o,
                                   Z, ln_z_scale, ln_z_bias, W_b);
    gemm_proj_mma<<<dim3(EPROJ / 128, NROWS / 128), 256, PSMEM>>>();
    attn_mma<<<dim3(NHEAD, NSEQ), 256, ATTN_SMEM>>>(M_mask, gbias);
    gemm_out_mma<<<dim3(256 / 128, NROWS / 128), 256, PSMEM>>>(M_raw, out_bias, out);
}

// round 11
// speedup vs baseline: 1.6833x; 1.0117x over previous
#include <cuda_runtime.h>
#include <cuda_fp16.h>
#include <cstdint>
#include <math.h>

// Problem constants
#define D_NODE 256
#define D_PAIR 128
#define NHEAD  8
#define NSEQ   128
#define NRES   256
#define NROWS  (NSEQ * NRES)          // 32768
#define EPROJ  1024                    // 768 qkv + 256 gate

#define LOG2E 1.4426950408889634f

// Scratch (all fp16 single-precision operands)
__device__ __half g_M[(size_t)NROWS * D_NODE];       // LN(M)
__device__ __half g_W[(size_t)EPROJ * D_NODE];       // [Wqkv;Wgate]
__device__ __half g_O[(size_t)D_NODE * D_NODE];      // W_o
__device__ __half g_X[(size_t)NROWS * 768];          // q(scaled)|k|v
__device__ __half g_gate[(size_t)NROWS * 256];       // gate logits
__device__ __half g_pb[(size_t)NHEAD * NRES * NRES]; // pair bias*log2e [h][q][k]
__device__ __half g_A[(size_t)NROWS * D_NODE];       // gated attn out

__device__ __forceinline__ uint32_t smem_u32(const void* p) {
    uint32_t a;
    asm("{ .reg .u64 t; cvta.to.shared.u64 t, %1; cvt.u32.u64 %0, t; }"
        : "=r"(a) : "l"(p));
    return a;
}

#define LDM_X4(r0, r1, r2, r3, addr)                                           \
    asm volatile("ldmatrix.sync.aligned.m8n8.x4.shared.b16 {%0,%1,%2,%3}, [%4];" \
                 : "=r"(r0), "=r"(r1), "=r"(r2), "=r"(r3) : "r"(addr))
#define LDM_A(v, addr) LDM_X4((v)[0], (v)[1], (v)[2], (v)[3], addr)

#define LDM_T(v, addr)                                                         \
    asm volatile("ldmatrix.sync.aligned.m8n8.x4.trans.shared.b16 {%0,%1,%2,%3}, [%4];" \
                 : "=r"((v)[0]), "=r"((v)[1]), "=r"((v)[2]), "=r"((v)[3]) : "r"(addr))

#define MMA_F16(d, a, b0, b1)                                                  \
    asm volatile("mma.sync.aligned.m16n8k16.row.col.f32.f16.f16.f32 "          \
                 "{%0,%1,%2,%3}, {%4,%5,%6,%7}, {%8,%9}, {%0,%1,%2,%3};"       \
                 : "+f"((d)[0]), "+f"((d)[1]), "+f"((d)[2]), "+f"((d)[3])      \
                 : "r"((a)[0]), "r"((a)[1]), "r"((a)[2]), "r"((a)[3]),         \
                   "r"(b0), "r"(b1))

#define CP16(s, g)                                                             \
    asm volatile("cp.async.cg.shared.global [%0], [%1], 16;" :: "r"(s), "l"(g))
#define CP_COMMIT() asm volatile("cp.async.commit_group;" ::: "memory")

__device__ __forceinline__ uint32_t pk2(float lo, float hi) {
    __half2 h = __floats2half2_rn(lo, hi);      // .x = lo (low half)
    return *reinterpret_cast<uint32_t*>(&h);
}
__device__ __forceinline__ float2 h2f2(uint32_t u) {
    __half2 h = *reinterpret_cast<__half2*>(&u);
    return __half22float2(h);
}
__device__ __forceinline__ float ex2(float x) {
    float r;
    asm("ex2.approx.f32 %0, %1;" : "=f"(r) : "f"(x));
    return r;
}
__device__ __forceinline__ uint32_t ex2_h2(uint32_t x) {
    uint32_t r;
    asm("ex2.approx.f16x2 %0, %1;" : "=r"(r) : "r"(x));
    return r;
}

__device__ __forceinline__ float warp_sum(float v) {
#pragma unroll
    for (int o = 16; o > 0; o >>= 1) v += __shfl_xor_sync(0xffffffffu, v, o);
    return v;
}

// ---------------------------------------------------------------------------
// Kernel 1 (fused preprocessing): ln_m | wconv | wconv_o | pair  -> fp16
// ---------------------------------------------------------------------------
#define PREP_LN  4096
#define PREP_WC  (PREP_LN + 1024)   // 5120
#define PREP_WO  (PREP_WC + 256)    // 5376
#define PREP_TOT (PREP_WO + 8192)   // 13568

__global__ __launch_bounds__(256) void prep_kernel(
    const float* __restrict__ M_raw, const float* __restrict__ mlsc,
    const float* __restrict__ mlbi,
    const float* __restrict__ Wq, const float* __restrict__ Wg,
    const float* __restrict__ Wo,
    const float* __restrict__ Z, const float* __restrict__ zsc,
    const float* __restrict__ zbi, const float* __restrict__ Wb)
{
    __shared__ float swb[1024];
    __shared__ float ssc[128], sbi[128];
    __shared__ float spb[64];

    int b = blockIdx.x;
    int tid = threadIdx.x;

    if (b < PREP_LN) {
        int w = tid >> 5, l = tid & 31;
        int row = b * 8 + w;
        const float4* xr = (const float4*)(M_raw + (size_t)row * 256);
        float4 a = xr[l], bb = xr[l + 32];
        float s1 = (a.x + a.y) + (a.z + a.w) + (bb.x + bb.y) + (bb.z + bb.w);
        float s2 = a.x * a.x + a.y * a.y + a.z * a.z + a.w * a.w
                 + bb.x * bb.x + bb.y * bb.y + bb.z * bb.z + bb.w * bb.w;
        s1 = warp_sum(s1);
        s2 = warp_sum(s2);
        float mu  = s1 * (1.0f / 256.0f);
        float var = s2 * (1.0f / 256.0f) - mu * mu;
        float inv = rsqrtf(var + 1e-5f);

        float4 sa = ((const float4*)mlsc)[l], sb4 = ((const float4*)mlsc)[l + 32];
        float4 ba = ((const float4*)mlbi)[l], bb4 = ((const float4*)mlbi)[l + 32];

        __half* mh = g_M + (size_t)row * 256;
        {
            int c = l * 4;
            *(__half2*)(mh + c) = __floats2half2_rn(
                (a.x - mu) * inv * sa.x + ba.x, (a.y - mu) * inv * sa.y + ba.y);
            *(__half2*)(mh + c + 2) = __floats2half2_rn(
                (a.z - mu) * inv * sa.z + ba.z, (a.w - mu) * inv * sa.w + ba.w);
            c += 128;
            *(__half2*)(mh + c) = __floats2half2_rn(
                (bb.x - mu) * inv * sb4.x + bb4.x, (bb.y - mu) * inv * sb4.y + bb4.y);
            *(__half2*)(mh + c + 2) = __floats2half2_rn(
                (bb.z - mu) * inv * sb4.z + bb4.z, (bb.w - mu) * inv * sb4.w + bb4.w);
        }
    } else if (b < PREP_WC) {
        int i = (b - PREP_LN) * 256 + tid;
        float v = (i < 768 * 256) ? Wq[i] : Wg[i - 768 * 256];
        g_W[i] = __float2half_rn(v);
    } else if (b < PREP_WO) {
        int i = (b - PREP_WC) * 256 + tid;
        g_O[i] = __float2half_rn(Wo[i]);
    } else {
        int pb = b - PREP_WO;
        if (tid < 128) { ssc[tid] = zsc[tid]; sbi[tid] = zbi[tid]; }
        ((float4*)swb)[tid] = ((const float4*)Wb)[tid];
        __syncthreads();

        int w = tid >> 5, l = tid & 31;
        int row = pb * 8 + w;                // = q*256 + k
        float4 z = ((const float4*)(Z + (size_t)row * 128))[l];
        float s1 = (z.x + z.y) + (z.z + z.w);
        float s2 = z.x * z.x + z.y * z.y + z.z * z.z + z.w * z.w;
        s1 = warp_sum(s1);
        s2 = warp_sum(s2);
        float mu  = s1 * (1.0f / 128.0f);
        float var = s2 * (1.0f / 128.0f) - mu * mu;
        float inv = rsqrtf(var + 1e-5f);
        int c = l * 4;
        float zn0 = (z.x - mu) * inv * ssc[c]     + sbi[c];
        float zn1 = (z.y - mu) * inv * ssc[c + 1] + sbi[c + 1];
        float zn2 = (z.z - mu) * inv * ssc[c + 2] + sbi[c + 2];
        float zn3 = (z.w - mu) * inv * ssc[c + 3] + sbi[c + 3];

        float p[8];
#pragma unroll
        for (int hh = 0; hh < 8; hh++) {
            float4 wb4 = ((const float4*)swb)[hh * 32 + l];
            p[hh] = zn0 * wb4.x + zn1 * wb4.y + zn2 * wb4.z + zn3 * wb4.w;
        }
#pragma unroll
        for (int hh = 0; hh < 8; hh++) p[hh] += __shfl_xor_sync(0xffffffffu, p[hh], 16);
        float q0 = (l & 16) ? p[4] : p[0];
        float q1 = (l & 16) ? p[5] : p[1];
        float q2 = (l & 16) ? p[6] : p[2];
        float q3 = (l & 16) ? p[7] : p[3];
        q0 += __shfl_xor_sync(0xffffffffu, q0, 8);
        q1 += __shfl_xor_sync(0xffffffffu, q1, 8);
        q2 += __shfl_xor_sync(0xffffffffu, q2, 8);
        q3 += __shfl_xor_sync(0xffffffffu, q3, 8);
        float r0 = (l & 8) ? q2 : q0;
        float r1 = (l & 8) ? q3 : q1;
        r0 += __shfl_xor_sync(0xffffffffu, r0, 4);
        r1 += __shfl_xor_sync(0xffffffffu, r1, 4);
        float s0 = (l & 4) ? r1 : r0;
        s0 += __shfl_xor_sync(0xffffffffu, s0, 2);
        s0 += __shfl_xor_sync(0xffffffffu, s0, 1);
        if ((l & 3) == 0) spb[w * 8 + (l >> 2)] = s0 * LOG2E;
        __syncthreads();
        if (tid < 64) {
            int hh = tid >> 3, j = tid & 7;
            int row0 = pb * 8;
            int qq = row0 >> 8, k0 = row0 & 255;
            g_pb[(size_t)hh * 65536 + qq * 256 + k0 + j] = __float2half_rn(spb[j * 8 + hh]);
        }
    }
}

// ---------------------------------------------------------------------------
// Kernel 3: projection GEMM (mma.sync fp16 single-term, cp.async 2-stage).
// ---------------------------------------------------------------------------
#define PSTG_A 0
#define PSTG_B 10240
#define PSTAGE 20480
#define PSMEM  (2 * PSTAGE)

__global__ __launch_bounds__(256) void gemm_proj_mma()
{
    extern __shared__ __align__(16) unsigned char smb[];
    uint32_t sbase = smem_u32(smb);
    int tid = threadIdx.x;
    int lane = tid & 31, wid = tid >> 5;
    int wm = wid >> 2, wn = wid & 3;
    int bm = blockIdx.y * 128, bn = blockIdx.x * 128;

    float acc[4][4][4] = {};

    int lrow = tid >> 1, lhalf = tid & 1;
    size_t gA = (size_t)(bm + lrow) * 256 + lhalf * 16;
    size_t gB = (size_t)(bn + lrow) * 256 + lhalf * 16;
    uint32_t sOff = lrow * 80 + lhalf * 32;

    uint32_t aRow = (lane & 15);
    uint32_t aChunk = (lane >> 4) << 3;
    uint32_t bRow = (lane & 7) + ((lane >> 4) << 3);
    uint32_t bChunk = ((lane >> 3) & 1) << 3;

    {
        uint32_t b = sbase;
        CP16(b + PSTG_A + sOff, g_M + gA); CP16(b + PSTG_A + sOff + 16, g_M + gA + 8);
        CP16(b + PSTG_B + sOff, g_W + gB); CP16(b + PSTG_B + sOff + 16, g_W + gB + 8);
        CP_COMMIT();
    }

#pragma unroll 1
    for (int t = 0; t < 8; t++) {
        if (t < 7) {
            int c = t + 1;
            uint32_t b = sbase + (c & 1) * PSTAGE;
            const __half* p;
            p = g_M + gA + c * 32;
            CP16(b + PSTG_A + sOff, p); CP16(b + PSTG_A + sOff + 16, p + 8);
            p = g_W + gB + c * 32;
            CP16(b + PSTG_B + sOff, p); CP16(b + PSTG_B + sOff + 16, p + 8);
            CP_COMMIT();
            asm volatile("cp.async.wait_group 1;" ::: "memory");
        } else {
            asm volatile("cp.async.wait_group 0;" ::: "memory");
        }
        __syncthreads();

        uint32_t sb = sbase + (t & 1) * PSTAGE;
#pragma unroll
        for (int ks = 0; ks < 2; ks++) {
            uint32_t ah[4][4], bh[2][4];
#pragma unroll
            for (int mi = 0; mi < 4; mi++) {
                uint32_t ad = sb + PSTG_A + (wm * 64 + mi * 16 + aRow) * 80
                            + (ks * 16 + aChunk) * 2;
                LDM_A(ah[mi], ad);
            }
#pragma unroll
            for (int ng = 0; ng < 2; ng++) {
                uint32_t bd = sb + PSTG_B + (wn * 32 + ng * 16 + bRow) * 80
                            + (ks * 16 + bChunk) * 2;
                LDM_A(bh[ng], bd);
            }
#pragma unroll
            for (int mi = 0; mi < 4; mi++) {
#pragma unroll
                for (int nj = 0; nj < 4; nj++) {
                    int ng = nj >> 1, sub = (nj & 1) * 2;
                    MMA_F16(acc[mi][nj], ah[mi], bh[ng][sub], bh[ng][sub + 1]);
                }
            }
        }
        __syncthreads();
    }

    int r0 = bm + wm * 64 + (lane >> 2);
    int c0 = bn + wn * 32 + (lane & 3) * 2;
    if (bn < 768) {
        float sc = (bn < 256) ? (0.17677669529663688f * LOG2E) : 1.0f;
#pragma unroll
        for (int mi = 0; mi < 4; mi++) {
#pragma unroll
            for (int nj = 0; nj < 4; nj++) {
                int c = c0 + nj * 8;
#pragma unroll
                for (int p = 0; p < 2; p++) {
                    int r = r0 + mi * 16 + p * 8;
                    *(__half2*)(g_X + (size_t)r * 768 + c) =
                        __floats2half2_rn(acc[mi][nj][2 * p] * sc,
                                          acc[mi][nj][2 * p + 1] * sc);
                }
            }
        }
    } else {
#pragma unroll
        for (int mi = 0; mi < 4; mi++) {
#pragma unroll
            for (int nj = 0; nj < 4; nj++) {
                int c = c0 + nj * 8 - 768;
#pragma unroll
                for (int p = 0; p < 2; p++) {
                    int r = r0 + mi * 16 + p * 8;
                    *(__half2*)(g_gate + (size_t)r * 256 + c) =
                        __floats2half2_rn(acc[mi][nj][2 * p], acc[mi][nj][2 * p + 1]);
                }
            }
        }
    }
}

// ---------------------------------------------------------------------------
// Kernel 4: flash attention, fp16 single-term, f16x2 softmax exp.
// ---------------------------------------------------------------------------
#define OQ  0
#define OK  20480
#define OV  40960
#define OPB 61440
#define PBSTRIDE 36864
#define OMB (OPB + 2 * PBSTRIDE)      // 135168
#define ATTN_SMEM (OMB + 1024)        // 136192

__global__ __launch_bounds__(256) void attn_mma(
    const float* __restrict__ mask, const float* __restrict__ gbias)
{
    extern __shared__ __align__(16) unsigned char smb[];
    uint32_t sb = smem_u32(smb);
    int tid = threadIdx.x;
    int lane = tid & 31, w = tid >> 5;
    int h = blockIdx.x, s = blockIdx.y;

    const __half* XB = g_X + (size_t)s * 256 * 768;

#pragma unroll 1
    for (int i = tid; i < 1024; i += 256) {
        int r = i >> 2, seg = i & 3;
        uint32_t d = r * 80 + seg * 16;
        size_t off = (size_t)r * 768 + h * 32 + seg * 8;
        CP16(sb + OQ + d, XB + off);
        CP16(sb + OK + d, XB + off + 256);
        CP16(sb + OV + d, XB + off + 512);
    }
    {
        const __half* pbB = g_pb + (size_t)h * 65536;
#pragma unroll 1
        for (int i = tid; i < 2048; i += 256) {
            int q = i >> 3, seg = i & 7;
            CP16(sb + OPB + q * 144 + seg * 16, pbB + (size_t)q * 256 + seg * 8);
        }
    }
    CP_COMMIT();
    ((float*)(smb + OMB))[tid] = (1e9f * LOG2E) * (mask[s * 256 + tid] - 1.0f);
    asm volatile("cp.async.wait_group 0;" ::: "memory");
    __syncthreads();

    uint32_t aRow = lane & 15, aChunk = (lane >> 4) << 3;
    uint32_t bRow = (lane & 7) + ((lane >> 4) << 3);
    uint32_t bChunk = ((lane >> 3) & 1) << 3;
    uint32_t vkRow = (lane & 7) + (((lane >> 3) & 1) << 3);
    uint32_t vcCol = (lane >> 4) << 3;

    uint32_t ah[2][2][4];
#pragma unroll
    for (int mi = 0; mi < 2; mi++)
#pragma unroll
        for (int ks = 0; ks < 2; ks++) {
            uint32_t ad = sb + OQ + (w * 32 + mi * 16 + aRow) * 80
                        + (ks * 16 + aChunk) * 2;
            LDM_A(ah[mi][ks], ad);
        }

    float o[2][4][4] = {};
    float mrow[4] = {-1e30f, -1e30f, -1e30f, -1e30f};
    float srow[4] = {};

#pragma unroll 1
    for (int kb = 0; kb < 4; kb++) {
        if (kb < 3) {
            const __half* pbB = g_pb + (size_t)h * 65536 + (kb + 1) * 64;
            uint32_t dst = sb + OPB + ((kb + 1) & 1) * PBSTRIDE;
#pragma unroll 1
            for (int i = tid; i < 2048; i += 256) {
                int q = i >> 3, seg = i & 7;
                CP16(dst + q * 144 + seg * 16, pbB + (size_t)q * 256 + seg * 8);
            }
            CP_COMMIT();
            asm volatile("cp.async.wait_group 1;" ::: "memory");
        } else {
            asm volatile("cp.async.wait_group 0;" ::: "memory");
        }
        __syncthreads();

        float sfr[2][8][4] = {};
        // S = Q K^T (single fp16 term)
#pragma unroll
        for (int ks = 0; ks < 2; ks++)
#pragma unroll
            for (int ng = 0; ng < 4; ng++) {
                uint32_t kh[4];
                uint32_t bd = sb + OK + (kb * 64 + ng * 16 + bRow) * 80
                            + (ks * 16 + bChunk) * 2;
                LDM_A(kh, bd);
#pragma unroll
                for (int mi = 0; mi < 2; mi++) {
                    MMA_F16(sfr[mi][ng * 2], ah[mi][ks], kh[0], kh[1]);
                    MMA_F16(sfr[mi][ng * 2 + 1], ah[mi][ks], kh[2], kh[3]);
                }
            }

        // add mask bias + pair bias
        uint32_t pbuf = sb + OPB + (kb & 1) * PBSTRIDE;
        const float* mbp = (const float*)(smb + OMB) + kb * 64;
#pragma unroll
        for (int mi = 0; mi < 2; mi++) {
            int q0 = w * 32 + mi * 16 + (lane >> 2);
#pragma unroll
            for (int nj = 0; nj < 8; nj++) {
                int cB = nj * 8 + (lane & 3) * 2;
                float2 mv = *(const float2*)(mbp + cB);
                uint32_t u0, u1;
                asm("ld.shared.b32 %0, [%1];" : "=r"(u0) : "r"(pbuf + q0 * 144 + cB * 2));
                asm("ld.shared.b32 %0, [%1];" : "=r"(u1) : "r"(pbuf + (q0 + 8) * 144 + cB * 2));
                float2 p0 = h2f2(u0), p1 = h2f2(u1);
                sfr[mi][nj][0] += mv.x + p0.x;
                sfr[mi][nj][1] += mv.y + p0.y;
                sfr[mi][nj][2] += mv.x + p1.x;
                sfr[mi][nj][3] += mv.y + p1.y;
            }
        }

        // online softmax: exp via f16x2 MUFU, result doubles as PV A-operand.
        // packed exp stored into sfr[mi][nj][2p] (slot 2p+1 becomes dead).
#pragma unroll
        for (int mi = 0; mi < 2; mi++)
#pragma unroll
            for (int p = 0; p < 2; p++) {
                int id = mi * 2 + p;
                float mx = mrow[id];
#pragma unroll
                for (int nj = 0; nj < 8; nj++)
                    mx = fmaxf(mx, fmaxf(sfr[mi][nj][2 * p], sfr[mi][nj][2 * p + 1]));
                mx = fmaxf(mx, __shfl_xor_sync(0xffffffffu, mx, 1));
                mx = fmaxf(mx, __shfl_xor_sync(0xffffffffu, mx, 2));
                float es = ex2(mrow[id] - mx);
                mrow[id] = mx;
                float ls = 0.f;
#pragma unroll
                for (int nj = 0; nj < 8; nj++) {
                    uint32_t pe = ex2_h2(pk2(sfr[mi][nj][2 * p] - mx,
                                             sfr[mi][nj][2 * p + 1] - mx));
                    float2 pf = h2f2(pe);
                    ls += pf.x + pf.y;
                    sfr[mi][nj][2 * p] = __uint_as_float(pe);
                }
                ls += __shfl_xor_sync(0xffffffffu, ls, 1);
                ls += __shfl_xor_sync(0xffffffffu, ls, 2);
                srow[id] = srow[id] * es + ls;
#pragma unroll
                for (int nc = 0; nc < 4; nc++) {
                    o[mi][nc][2 * p] *= es;
                    o[mi][nc][2 * p + 1] *= es;
                }
            }

        // O += P V (P already packed fp16 in sfr[..][0]/[2])
#pragma unroll
        for (int t = 0; t < 4; t++) {
            uint32_t pa[2][4];
#pragma unroll
            for (int mi = 0; mi < 2; mi++) {
                pa[mi][0] = __float_as_uint(sfr[mi][2 * t][0]);
                pa[mi][1] = __float_as_uint(sfr[mi][2 * t][2]);
                pa[mi][2] = __float_as_uint(sfr[mi][2 * t + 1][0]);
                pa[mi][3] = __float_as_uint(sfr[mi][2 * t + 1][2]);
            }
#pragma unroll
            for (int ng = 0; ng < 2; ng++) {
                uint32_t vh[4];
                uint32_t vd = sb + OV + (kb * 64 + t * 16 + vkRow) * 80
                            + (ng * 16 + vcCol) * 2;
                LDM_T(vh, vd);
#pragma unroll
                for (int mi = 0; mi < 2; mi++) {
                    MMA_F16(o[mi][ng * 2], pa[mi], vh[0], vh[1]);
                    MMA_F16(o[mi][ng * 2 + 1], pa[mi], vh[2], vh[3]);
                }
            }
        }
        __syncthreads();
    }

    // epilogue part 1: stage normalized O in smem (fp32, row stride 36 floats)
    float* stg = (float*)smb;
#pragma unroll
    for (int mi = 0; mi < 2; mi++)
#pragma unroll
        for (int p = 0; p < 2; p++) {
            float inv = 1.0f / srow[mi * 2 + p];
            int rr = w * 32 + mi * 16 + (lane >> 2) + p * 8;
#pragma unroll
            for (int nc = 0; nc < 4; nc++) {
                int cc = nc * 8 + (lane & 3) * 2;
                *(float2*)(stg + rr * 36 + cc) =
                    make_float2(o[mi][nc][2 * p] * inv, o[mi][nc][2 * p + 1] * inv);
            }
        }
    __syncthreads();

    // epilogue part 2: coalesced gated write-out (8 lanes cover one row)
    {
        int seg = tid & 7;            // 4 channels per thread
        int rbase = tid >> 3;         // 32 rows per pass
        int gc = h * 32 + seg * 4;
        float4 gb4 = *(const float4*)(gbias + gc);
#pragma unroll
        for (int pass = 0; pass < 8; pass++) {
            int rr = pass * 32 + rbase;
            size_t gr = (size_t)(s * 256 + rr) * 256 + gc;
            float4 ov = *(float4*)(stg + rr * 36 + seg * 4);
            uint2 gu = *(const uint2*)(g_gate + gr);
            float2 gl0 = h2f2(gu.x), gl1 = h2f2(gu.y);
            float a0 = ov.x / (1.0f + __expf(-(gl0.x + gb4.x)));
            float a1 = ov.y / (1.0f + __expf(-(gl0.y + gb4.y)));
            float a2 = ov.z / (1.0f + __expf(-(gl1.x + gb4.z)));
            float a3 = ov.w / (1.0f + __expf(-(gl1.y + gb4.w)));
            uint2 hv;
            hv.x = pk2(a0, a1);
            hv.y = pk2(a2, a3);
            *(uint2*)(g_A + gr) = hv;
        }
    }
}

// ---------------------------------------------------------------------------
// Kernel 5: out = A @ W_o^T + M_raw + out_bias.
// BM=128 BN=64 (1024 CTAs, small acc footprint -> high occupancy).
// ---------------------------------------------------------------------------
#define GO_A 0
#define GO_B 10240
#define GO_STAGE 15360
#define GO_SMEM  (2 * GO_STAGE)   // 30720

__global__ __launch_bounds__(256) void gemm_out_mma(
    const float* __restrict__ Mraw, const float* __restrict__ obias,
    float* __restrict__ out)
{
    extern __shared__ __align__(16) unsigned char smb[];
    uint32_t sbase = smem_u32(smb);
    int tid = threadIdx.x;
    int lane = tid & 31, wid = tid >> 5;
    int wm = wid >> 1, wn = wid & 1;           // 4 x 2 warp grid
    int bm = blockIdx.y * 128, bn = blockIdx.x * 64;

    float acc[2][4][4] = {};

    int lrow = tid >> 1, lhalf = tid & 1;
    size_t gA = (size_t)(bm + lrow) * 256 + lhalf * 16;
    uint32_t sOffA = lrow * 80 + lhalf * 32;
    // B: 64 rows, loaded by threads 0..127
    size_t gB = (size_t)(bn + (lrow & 63)) * 256 + lhalf * 16;
    uint32_t sOffB = (lrow & 63) * 80 + lhalf * 32;
    bool doB = (tid < 128);

    uint32_t aRow = (lane & 15);
    uint32_t aChunk = (lane >> 4) << 3;
    uint32_t bRow = (lane & 7) + ((lane >> 4) << 3);
    uint32_t bChunk = ((lane >> 3) & 1) << 3;

    {
        uint32_t b = sbase;
        CP16(b + GO_A + sOffA, g_A + gA); CP16(b + GO_A + sOffA + 16, g_A + gA + 8);
        if (doB) {
            CP16(b + GO_B + sOffB, g_O + gB); CP16(b + GO_B + sOffB + 16, g_O + gB + 8);
        }
        CP_COMMIT();
    }

#pragma unroll 1
    for (int t = 0; t < 8; t++) {
        if (t < 7) {
            int c = t + 1;
            uint32_t b = sbase + (c & 1) * GO_STAGE;
            const __half* p;
            p = g_A + gA + c * 32;
            CP16(b + GO_A + sOffA, p); CP16(b + GO_A + sOffA + 16, p + 8);
            if (doB) {
                p = g_O + gB + c * 32;
                CP16(b + GO_B + sOffB, p); CP16(b + GO_B + sOffB + 16, p + 8);
            }
            CP_COMMIT();
            asm volatile("cp.async.wait_group 1;" ::: "memory");
        } else {
            asm volatile("cp.async.wait_group 0;" ::: "memory");
        }
        __syncthreads();

        uint32_t sb = sbase + (t & 1) * GO_STAGE;
#pragma unroll
        for (int ks = 0; ks < 2; ks++) {
            uint32_t ah[2][4], bh[2][4];
#pragma unroll
            for (int mi = 0; mi < 2; mi++) {
                uint32_t ad = sb + GO_A + (wm * 32 + mi * 16 + aRow) * 80
                            + (ks * 16 + aChunk) * 2;
                LDM_A(ah[mi], ad);
            }
#pragma unroll
            for (int ng = 0; ng < 2; ng++) {
                uint32_t bd = sb + GO_B + (wn * 32 + ng * 16 + bRow) * 80
                            + (ks * 16 + bChunk) * 2;
                LDM_A(bh[ng], bd);
            }
#pragma unroll
            for (int mi = 0; mi < 2; mi++) {
#pragma unroll
                for (int nj = 0; nj < 4; nj++) {
                    int ng = nj >> 1, sub = (nj & 1) * 2;
                    MMA_F16(acc[mi][nj], ah[mi], bh[ng][sub], bh[ng][sub + 1]);
                }
            }
        }
        __syncthreads();
    }

    int r0 = bm + wm * 32 + (lane >> 2);
    int c0 = bn + wn * 32 + (lane & 3) * 2;
#pragma unroll
    for (int mi = 0; mi < 2; mi++) {
#pragma unroll
        for (int nj = 0; nj < 4; nj++) {
            int r = r0 + mi * 16, c = c0 + nj * 8;
            float ob0 = obias[c], ob1 = obias[c + 1];
            float2 m0 = *(const float2*)(Mraw + (size_t)r * 256 + c);
            *(float2*)(out + (size_t)r * 256 + c) =
                make_float2(acc[mi][nj][0] + m0.x + ob0, acc[mi][nj][1] + m0.y + ob1);
            float2 m1 = *(const float2*)(Mraw + (size_t)(r + 8) * 256 + c);
            *(float2*)(out + (size_t)(r + 8) * 256 + c) =
                make_float2(acc[mi][nj][2] + m1.x + ob0, acc[mi][nj][3] + m1.y + ob1);
        }
    }
}

// ---------------------------------------------------------------------------
extern "C" void kernel_launch(void* const* d_in, const int* in_sizes, int n_in,
                              void* d_out, int out_size)
{
    const float* M_raw      = (const float*)d_in[0];
    const float* Z          = (const float*)d_in[1];
    const float* M_mask     = (const float*)d_in[2];
    const float* ln_m_scale = (const float*)d_in[3];
    const float* ln_m_bias  = (const float*)d_in[4];
    const float* ln_z_scale = (const float*)d_in[5];
    const float* ln_z_bias  = (const float*)d_in[6];
    const float* W_b        = (const float*)d_in[7];
    const float* W_qkv      = (const float*)d_in[8];
    const float* W_gate     = (const float*)d_in[9];
    const float* gbias      = (const float*)d_in[10];
    const float* W_o        = (const float*)d_in[11];
    const float* out_bias   = (const float*)d_in[12];
    float* out = (float*)d_out;

    cudaFuncSetAttribute(attn_mma, cudaFuncAttributeMaxDynamicSharedMemorySize,
                         ATTN_SMEM);

    prep_kernel<<<PREP_TOT, 256>>>(M_raw, ln_m_scale, ln_m_bias,
                                   W_qkv, W_gate, W_o,
                                   Z, ln_z_scale, ln_z_bias, W_b);
    gemm_proj_mma<<<dim3(EPROJ / 128, NROWS / 128), 256, PSMEM>>>();
    attn_mma<<<dim3(NHEAD, NSEQ), 256, ATTN_SMEM>>>(M_mask, gbias);
    gemm_out_mma<<<dim3(256 / 64, NROWS / 128), 256, GO_SMEM>>>(M_raw, out_bias, out);
}